// round 13
// baseline (speedup 1.0000x reference)
#include <cuda_runtime.h>
#include <cuda_fp16.h>
#include <math.h>
#include <stdint.h>

#define NN      100000
#define EE      1600000
#define NETOT   (EE + NN)           // edges + self loops
#define INC     128
#define C1      128                 // heads(4) * hid(32)
#define C2      64
#define HEADS   4
#define NGRAPH  64
#define NCLS    2
#define NCHUNK  ((NN + 255) / 256)  // 391
#define MB      64                  // gemm rows per block
#define SCAT_E8 (EE / 8)            // 200000 (exact)
#define LOG2E   1.44269504f

// ---------------- scratch (static __device__, no allocations) ----------------
__device__ int    g_deg[NN];        // zero at entry (BSS-zero; re-zeroed by scanC each call)
__device__ int    g_rs[NN + 1];
__device__ int    g_epos[EE];       // per-edge slot within its dst segment
__device__ int    g_csr[NETOT];
__device__ int    g_csum[512];
__device__ __align__(16) __half g_h1h[NN * C1];
__device__ float  g_as1[NN * HEADS];   // pre-scaled by log2(e)
__device__ float  g_ad1[NN * HEADS];   // pre-scaled by log2(e)
__device__ __align__(16) __half g_x2h[NN * C1];
__device__ __align__(16) __half g_h2h[NN * C2];
__device__ float  g_as2[NN];           // pre-scaled by log2(e)
__device__ float  g_ad2[NN];           // pre-scaled by log2(e)
__device__ __align__(16) __half g_out2h[NN * C2];
__device__ __align__(16) __half g_w1t[C1 * INC];   // W1^T fp16, ldsm-swizzled
__device__ __align__(16) __half g_w2t[C2 * C1];    // W2^T fp16, ldsm-swizzled

__device__ __forceinline__ float lrelu(float x) { return x > 0.f ? x : 0.2f * x; }
__device__ __forceinline__ float elu1(float x)  { return x > 0.f ? x : expm1f(x); }
__device__ __forceinline__ float ex2(float x) {
    float r;
    asm("ex2.approx.ftz.f32 %0, %1;" : "=f"(r) : "f"(x));
    return r;
}

__device__ __forceinline__ void ldsm4(uint32_t& r0, uint32_t& r1, uint32_t& r2, uint32_t& r3,
                                      uint32_t addr) {
    asm volatile("ldmatrix.sync.aligned.m8n8.x4.shared.b16 {%0,%1,%2,%3}, [%4];"
                 : "=r"(r0), "=r"(r1), "=r"(r2), "=r"(r3) : "r"(addr));
}
__device__ __forceinline__ void mma16816(float* c, const uint32_t* a, uint32_t b0, uint32_t b1) {
    asm volatile("mma.sync.aligned.m16n8k16.row.col.f32.f16.f16.f32 "
                 "{%0,%1,%2,%3},{%4,%5,%6,%7},{%8,%9},{%0,%1,%2,%3};"
                 : "+f"(c[0]), "+f"(c[1]), "+f"(c[2]), "+f"(c[3])
                 : "r"(a[0]), "r"(a[1]), "r"(a[2]), "r"(a[3]), "r"(b0), "r"(b1));
}

// ---------------- CSR build ----------------
// hist: 8 edges/thread, count degrees + record per-edge slot
__global__ void k_hist(const int* __restrict__ dst) {
    int t = blockIdx.x * blockDim.x + threadIdx.x;
    int e = t * 8;
    if (e + 7 < EE) {
        int4 d0 = *(const int4*)(dst + e);
        int4 d1 = *(const int4*)(dst + e + 4);
        int4 p0, p1;
        p0.x = atomicAdd(&g_deg[d0.x], 1);
        p0.y = atomicAdd(&g_deg[d0.y], 1);
        p0.z = atomicAdd(&g_deg[d0.z], 1);
        p0.w = atomicAdd(&g_deg[d0.w], 1);
        p1.x = atomicAdd(&g_deg[d1.x], 1);
        p1.y = atomicAdd(&g_deg[d1.y], 1);
        p1.z = atomicAdd(&g_deg[d1.z], 1);
        p1.w = atomicAdd(&g_deg[d1.w], 1);
        *(int4*)(g_epos + e) = p0;
        *(int4*)(g_epos + e + 4) = p1;
    } else {
        for (; e < EE; e++) g_epos[e] = atomicAdd(&g_deg[dst[e]], 1);
    }
}

__global__ void k_scanA() {
    __shared__ int sh[256];
    int i = blockIdx.x * 256 + threadIdx.x;
    int v = (i < NN) ? (g_deg[i] + 1) : 0;    // +1 = self loop
    sh[threadIdx.x] = v;
    __syncthreads();
    #pragma unroll
    for (int off = 1; off < 256; off <<= 1) {
        int t = (threadIdx.x >= off) ? sh[threadIdx.x - off] : 0;
        __syncthreads();
        sh[threadIdx.x] += t;
        __syncthreads();
    }
    if (i < NN) g_rs[i] = sh[threadIdx.x] - v;     // chunk-local exclusive
    if (threadIdx.x == 255) g_csum[blockIdx.x] = sh[255];
}

__global__ void __launch_bounds__(512) k_scanC() {
    __shared__ int sh[512];
    int t = threadIdx.x;
    int v = (t < NCHUNK) ? g_csum[t] : 0;
    sh[t] = v;
    __syncthreads();
    #pragma unroll
    for (int off = 1; off < 512; off <<= 1) {
        int tv = (t >= off) ? sh[t - off] : 0;
        __syncthreads();
        sh[t] += tv;
        __syncthreads();
    }
    sh[t] -= v;                                    // exclusive
    __syncthreads();
    int i = blockIdx.x * 512 + t;
    if (i < NN) {
        g_rs[i] += sh[i >> 8];
        g_deg[i] = 0;                              // reset for next invocation
    }
    if (i == 0) g_rs[NN] = NETOT;
}

// scatter: 8 edges/thread, no atomics
__global__ void k_scatter(const int* __restrict__ ei) {
    int idx = blockIdx.x * blockDim.x + threadIdx.x;
    if (idx < SCAT_E8) {
        int e = idx * 8;
        int4 s0 = *(const int4*)(ei + e);
        int4 s1 = *(const int4*)(ei + e + 4);
        int4 d0 = *(const int4*)(ei + EE + e);
        int4 d1 = *(const int4*)(ei + EE + e + 4);
        int4 p0 = *(const int4*)(g_epos + e);
        int4 p1 = *(const int4*)(g_epos + e + 4);
        int r0 = g_rs[d0.x], r1 = g_rs[d0.y], r2 = g_rs[d0.z], r3 = g_rs[d0.w];
        int r4 = g_rs[d1.x], r5 = g_rs[d1.y], r6 = g_rs[d1.z], r7 = g_rs[d1.w];
        g_csr[r0 + p0.x] = s0.x;
        g_csr[r1 + p0.y] = s0.y;
        g_csr[r2 + p0.z] = s0.z;
        g_csr[r3 + p0.w] = s0.w;
        g_csr[r4 + p1.x] = s1.x;
        g_csr[r5 + p1.y] = s1.y;
        g_csr[r6 + p1.z] = s1.z;
        g_csr[r7 + p1.w] = s1.w;
    } else {
        int n = idx - SCAT_E8;
        if (n < NN) g_csr[g_rs[n + 1] - 1] = n;    // self loop
    }
}

// one-time weight transpose + fp16 + ldsm swizzle bake
__global__ void k_prepW(const float* __restrict__ W1, const float* __restrict__ W2) {
    int idx = blockIdx.x * blockDim.x + threadIdx.x;
    if (idx < 128 * 16) {
        int n = idx >> 4, kc = idx & 15;
        int sc = kc ^ (n & 7);
        #pragma unroll
        for (int j = 0; j < 8; j++)
            g_w1t[n * 128 + (sc << 3) + j] = __float2half(W1[(kc * 8 + j) * C1 + n]);
    } else if (idx < 128 * 16 + 64 * 16) {
        int q = idx - 128 * 16;
        int n = q >> 4, kc = q & 15;
        int sc = kc ^ (n & 7);
        #pragma unroll
        for (int j = 0; j < 8; j++)
            g_w2t[n * 128 + (sc << 3) + j] = __float2half(W2[(kc * 8 + j) * C2 + n]);
    }
}

// ---------------- GEMM1 (HMMA): h1 = x @ W1, fp16 out + attention scalars ----------------
__global__ void __launch_bounds__(256) k_gemm1(
        const float* __restrict__ x,
        const float* __restrict__ att_s, const float* __restrict__ att_d) {
    __shared__ __align__(16) __half xs[MB * 128];     // 16KB; reused as stage buffer
    __shared__ __align__(16) __half ws[128 * 128];    // 32KB
    int tid = threadIdx.x;
    int row0 = blockIdx.x * MB;

    {
        const uint4* wsrc = (const uint4*)g_w1t;
        uint4* wdst = (uint4*)ws;
        #pragma unroll
        for (int i = 0; i < 8; i++) wdst[tid + 256 * i] = wsrc[tid + 256 * i];
    }
    #pragma unroll
    for (int i = 0; i < 4; i++) {
        int idx = tid + 256 * i;
        int m = idx >> 4, cc = idx & 15;
        int gm = row0 + m; if (gm > NN - 1) gm = NN - 1;
        const float4* xp = (const float4*)(x + gm * INC + cc * 8);
        float4 v0 = xp[0], v1 = xp[1];
        __half2 h0 = __floats2half2_rn(v0.x, v0.y);
        __half2 h1 = __floats2half2_rn(v0.z, v0.w);
        __half2 h2 = __floats2half2_rn(v1.x, v1.y);
        __half2 h3 = __floats2half2_rn(v1.z, v1.w);
        uint4 pk = make_uint4(*(unsigned*)&h0, *(unsigned*)&h1, *(unsigned*)&h2, *(unsigned*)&h3);
        int sc = cc ^ (m & 7);
        *(uint4*)(xs + m * 128 + sc * 8) = pk;
    }
    __syncthreads();

    int w = tid >> 5, lane = tid & 31;
    int mw = w >> 2, nw = w & 3;
    int i8 = lane >> 3, r8 = lane & 7;
    uint32_t xbase = (uint32_t)__cvta_generic_to_shared(xs);
    uint32_t wbase = (uint32_t)__cvta_generic_to_shared(ws);

    int rowA[2], rowB[2];
    #pragma unroll
    for (int mt = 0; mt < 2; mt++) rowA[mt] = mw * 32 + mt * 16 + (i8 & 1) * 8 + r8;
    #pragma unroll
    for (int p = 0; p < 2; p++)   rowB[p] = nw * 32 + p * 16 + (i8 >> 1) * 8 + r8;
    int kcA_off = (i8 >> 1);
    int kcB_off = (i8 & 1);

    float c[2][4][4];
    #pragma unroll
    for (int mt = 0; mt < 2; mt++)
        #pragma unroll
        for (int nt = 0; nt < 4; nt++)
            #pragma unroll
            for (int q = 0; q < 4; q++) c[mt][nt][q] = 0.f;

    #pragma unroll
    for (int kt = 0; kt < 8; kt++) {
        uint32_t A[2][4], B[2][4];
        #pragma unroll
        for (int mt = 0; mt < 2; mt++) {
            int kc = kt * 2 + kcA_off;
            uint32_t addr = xbase + rowA[mt] * 256 + (((kc ^ (rowA[mt] & 7))) << 4);
            ldsm4(A[mt][0], A[mt][1], A[mt][2], A[mt][3], addr);
        }
        #pragma unroll
        for (int p = 0; p < 2; p++) {
            int kc = kt * 2 + kcB_off;
            uint32_t addr = wbase + rowB[p] * 256 + (((kc ^ (rowB[p] & 7))) << 4);
            ldsm4(B[p][0], B[p][1], B[p][2], B[p][3], addr);
        }
        #pragma unroll
        for (int mt = 0; mt < 2; mt++) {
            mma16816(c[mt][0], A[mt], B[0][0], B[0][1]);
            mma16816(c[mt][1], A[mt], B[0][2], B[0][3]);
            mma16816(c[mt][2], A[mt], B[1][0], B[1][1]);
            mma16816(c[mt][3], A[mt], B[1][2], B[1][3]);
        }
    }
    __syncthreads();                                   // xs reads done; reuse as stage

    uint32_t* stg = (uint32_t*)xs;                     // 64 rows x 64 words
    int quad = lane & 3;
    #pragma unroll
    for (int mt = 0; mt < 2; mt++) {
        int rlo_l = mw * 32 + mt * 16 + (lane >> 2);
        int rhi_l = rlo_l + 8;
        int rlo = row0 + rlo_l, rhi = row0 + rhi_l;
        int sw = (rlo_l & 7) << 2;                     // same for rhi_l
        float slo = 0.f, shi = 0.f, dlo = 0.f, dhi = 0.f;
        #pragma unroll
        for (int nt = 0; nt < 4; nt++) {
            int cb = nw * 32 + nt * 8 + 2 * quad;
            float as0 = att_s[cb], as1 = att_s[cb + 1];
            float ad0 = att_d[cb], ad1 = att_d[cb + 1];
            float v0 = c[mt][nt][0], v1 = c[mt][nt][1];
            float v2 = c[mt][nt][2], v3 = c[mt][nt][3];
            slo += v0 * as0 + v1 * as1;  dlo += v0 * ad0 + v1 * ad1;
            shi += v2 * as0 + v3 * as1;  dhi += v2 * ad0 + v3 * ad1;
            int wcol = cb >> 1;
            __half2 hlo = __floats2half2_rn(v0, v1);
            __half2 hhi = __floats2half2_rn(v2, v3);
            stg[rlo_l * 64 + (wcol ^ sw)] = *(uint32_t*)&hlo;
            stg[rhi_l * 64 + (wcol ^ sw)] = *(uint32_t*)&hhi;
        }
        #pragma unroll
        for (int o = 1; o <= 2; o <<= 1) {
            slo += __shfl_xor_sync(0xffffffffu, slo, o);
            shi += __shfl_xor_sync(0xffffffffu, shi, o);
            dlo += __shfl_xor_sync(0xffffffffu, dlo, o);
            dhi += __shfl_xor_sync(0xffffffffu, dhi, o);
        }
        if (quad == 0) {
            if (rlo < NN) { g_as1[rlo * 4 + nw] = slo * LOG2E; g_ad1[rlo * 4 + nw] = dlo * LOG2E; }
            if (rhi < NN) { g_as1[rhi * 4 + nw] = shi * LOG2E; g_ad1[rhi * 4 + nw] = dhi * LOG2E; }
        }
    }
    __syncthreads();
    #pragma unroll
    for (int i = 0; i < 4; i++) {
        int q = tid + 256 * i;                         // 1024 uint4
        int row = q >> 4, w4 = q & 15;
        int grow = row0 + row;
        uint4 v = *(uint4*)&stg[row * 64 + ((4 * w4) ^ ((row & 7) << 2))];
        if (grow < NN) *(uint4*)(g_h1h + grow * C1 + 8 * w4) = v;
    }
}

// ---------------- conv1 aggregation: 2 edges/warp, 2 pairs in flight ----------------
__global__ void k_agg1(const float* __restrict__ b1) {
    int gw = (blockIdx.x * blockDim.x + threadIdx.x) >> 5;
    if (gw >= NN) return;
    int lane = threadIdx.x & 31;
    int half = lane >> 4, l16 = lane & 15;
    int colbase = l16 * 8;
    int head = l16 >> 2;
    float adh = g_ad1[gw * 4 + head];
    int beg = g_rs[gw], end = g_rs[gw + 1];

    float sum = 0.f;
    float acc[8];
    #pragma unroll
    for (int i = 0; i < 8; i++) acc[i] = 0.f;

    int j = beg;
    for (; j + 4 <= end; j += 4) {                     // 2 independent pairs in flight
        int sA = g_csr[j + half];
        int sB = g_csr[j + 2 + half];
        float aA = g_as1[sA * 4 + head];
        float aB = g_as1[sB * 4 + head];
        uint4 uA = *(const uint4*)(g_h1h + sA * C1 + colbase);
        uint4 uB = *(const uint4*)(g_h1h + sB * C1 + colbase);
        float eA = ex2(lrelu(aA + adh));
        float eB = ex2(lrelu(aB + adh));
        sum += eA + eB;
        float2 fA0 = __half22float2(*(__half2*)&uA.x), fA1 = __half22float2(*(__half2*)&uA.y);
        float2 fA2 = __half22float2(*(__half2*)&uA.z), fA3 = __half22float2(*(__half2*)&uA.w);
        float2 fB0 = __half22float2(*(__half2*)&uB.x), fB1 = __half22float2(*(__half2*)&uB.y);
        float2 fB2 = __half22float2(*(__half2*)&uB.z), fB3 = __half22float2(*(__half2*)&uB.w);
        acc[0] += eA * fA0.x + eB * fB0.x; acc[1] += eA * fA0.y + eB * fB0.y;
        acc[2] += eA * fA1.x + eB * fB1.x; acc[3] += eA * fA1.y + eB * fB1.y;
        acc[4] += eA * fA2.x + eB * fB2.x; acc[5] += eA * fA2.y + eB * fB2.y;
        acc[6] += eA * fA3.x + eB * fB3.x; acc[7] += eA * fA3.y + eB * fB3.y;
    }
    for (; j + 2 <= end; j += 2) {
        int s = g_csr[j + half];
        float a = g_as1[s * 4 + head];
        uint4 u = *(const uint4*)(g_h1h + s * C1 + colbase);
        float e = ex2(lrelu(a + adh));
        sum += e;
        float2 f0 = __half22float2(*(__half2*)&u.x);
        float2 f1 = __half22float2(*(__half2*)&u.y);
        float2 f2 = __half22float2(*(__half2*)&u.z);
        float2 f3 = __half22float2(*(__half2*)&u.w);
        acc[0] += e * f0.x; acc[1] += e * f0.y;
        acc[2] += e * f1.x; acc[3] += e * f1.y;
        acc[4] += e * f2.x; acc[5] += e * f2.y;
        acc[6] += e * f3.x; acc[7] += e * f3.y;
    }
    if (j < end && half == 0) {                        // odd tail: A-half only
        int s = g_csr[j];
        float a = g_as1[s * 4 + head];
        uint4 u = *(const uint4*)(g_h1h + s * C1 + colbase);
        float e = ex2(lrelu(a + adh));
        sum += e;
        float2 f0 = __half22float2(*(__half2*)&u.x);
        float2 f1 = __half22float2(*(__half2*)&u.y);
        float2 f2 = __half22float2(*(__half2*)&u.z);
        float2 f3 = __half22float2(*(__half2*)&u.w);
        acc[0] += e * f0.x; acc[1] += e * f0.y;
        acc[2] += e * f1.x; acc[3] += e * f1.y;
        acc[4] += e * f2.x; acc[5] += e * f2.y;
        acc[6] += e * f3.x; acc[7] += e * f3.y;
    }
    // merge the two halves
    sum += __shfl_xor_sync(0xffffffffu, sum, 16);
    #pragma unroll
    for (int i = 0; i < 8; i++) acc[i] += __shfl_xor_sync(0xffffffffu, acc[i], 16);

    if (half == 0) {
        float inv = 1.0f / (sum + 1e-16f);
        float4 bva = *(const float4*)(b1 + colbase);
        float4 bvb = *(const float4*)(b1 + colbase + 4);
        __half2 o0 = __floats2half2_rn(elu1(acc[0] * inv + bva.x), elu1(acc[1] * inv + bva.y));
        __half2 o1 = __floats2half2_rn(elu1(acc[2] * inv + bva.z), elu1(acc[3] * inv + bva.w));
        __half2 o2 = __floats2half2_rn(elu1(acc[4] * inv + bvb.x), elu1(acc[5] * inv + bvb.y));
        __half2 o3 = __floats2half2_rn(elu1(acc[6] * inv + bvb.z), elu1(acc[7] * inv + bvb.w));
        uint4 o = make_uint4(*(unsigned*)&o0, *(unsigned*)&o1, *(unsigned*)&o2, *(unsigned*)&o3);
        *(uint4*)(g_x2h + gw * C1 + colbase) = o;
    }
}

// ---------------- GEMM2 (HMMA): h2 = x2 @ W2, fp16 out + attention scalars ----------------
__global__ void __launch_bounds__(128) k_gemm2(
        const float* __restrict__ att_s, const float* __restrict__ att_d) {
    __shared__ __align__(16) __half xs[MB * 128];    // 16KB; reused as stage
    __shared__ __align__(16) __half ws[C2 * 128];    // 16KB
    __shared__ float s_part[2][MB], d_part[2][MB];
    int tid = threadIdx.x;
    int row0 = blockIdx.x * MB;

    {
        const uint4* wsrc = (const uint4*)g_w2t;
        uint4* wdst = (uint4*)ws;
        #pragma unroll
        for (int i = 0; i < 8; i++) wdst[tid + 128 * i] = wsrc[tid + 128 * i];
    }
    #pragma unroll
    for (int i = 0; i < 8; i++) {
        int idx = tid + 128 * i;
        int m = idx >> 4, cc = idx & 15;
        int gm = row0 + m; if (gm > NN - 1) gm = NN - 1;
        uint4 pk = *(const uint4*)(g_x2h + gm * C1 + cc * 8);
        int sc = cc ^ (m & 7);
        *(uint4*)(xs + m * 128 + sc * 8) = pk;
    }
    __syncthreads();

    int w = tid >> 5, lane = tid & 31;
    int mw = w >> 1, nw = w & 1;
    int i8 = lane >> 3, r8 = lane & 7;
    uint32_t xbase = (uint32_t)__cvta_generic_to_shared(xs);
    uint32_t wbase = (uint32_t)__cvta_generic_to_shared(ws);

    int rowA[2], rowB[2];
    #pragma unroll
    for (int mt = 0; mt < 2; mt++) rowA[mt] = mw * 32 + mt * 16 + (i8 & 1) * 8 + r8;
    #pragma unroll
    for (int p = 0; p < 2; p++)   rowB[p] = nw * 32 + p * 16 + (i8 >> 1) * 8 + r8;
    int kcA_off = (i8 >> 1), kcB_off = (i8 & 1);

    float c[2][4][4];
    #pragma unroll
    for (int mt = 0; mt < 2; mt++)
        #pragma unroll
        for (int nt = 0; nt < 4; nt++)
            #pragma unroll
            for (int q = 0; q < 4; q++) c[mt][nt][q] = 0.f;

    #pragma unroll
    for (int kt = 0; kt < 8; kt++) {
        uint32_t A[2][4], B[2][4];
        #pragma unroll
        for (int mt = 0; mt < 2; mt++) {
            int kc = kt * 2 + kcA_off;
            uint32_t addr = xbase + rowA[mt] * 256 + (((kc ^ (rowA[mt] & 7))) << 4);
            ldsm4(A[mt][0], A[mt][1], A[mt][2], A[mt][3], addr);
        }
        #pragma unroll
        for (int p = 0; p < 2; p++) {
            int kc = kt * 2 + kcB_off;
            uint32_t addr = wbase + rowB[p] * 256 + (((kc ^ (rowB[p] & 7))) << 4);
            ldsm4(B[p][0], B[p][1], B[p][2], B[p][3], addr);
        }
        #pragma unroll
        for (int mt = 0; mt < 2; mt++) {
            mma16816(c[mt][0], A[mt], B[0][0], B[0][1]);
            mma16816(c[mt][1], A[mt], B[0][2], B[0][3]);
            mma16816(c[mt][2], A[mt], B[1][0], B[1][1]);
            mma16816(c[mt][3], A[mt], B[1][2], B[1][3]);
        }
    }
    __syncthreads();                                   // xs reads done; reuse as stage

    uint32_t* stg = (uint32_t*)xs;                     // 64 rows x 32 words
    int quad = lane & 3;
    #pragma unroll
    for (int mt = 0; mt < 2; mt++) {
        int rlo_l = mw * 32 + mt * 16 + (lane >> 2);
        int rhi_l = rlo_l + 8;
        int sw = (rlo_l & 7) << 2;
        float slo = 0.f, shi = 0.f, dlo = 0.f, dhi = 0.f;
        #pragma unroll
        for (int nt = 0; nt < 4; nt++) {
            int cb = nw * 32 + nt * 8 + 2 * quad;
            float as0 = att_s[cb], as1 = att_s[cb + 1];
            float ad0 = att_d[cb], ad1 = att_d[cb + 1];
            float v0 = c[mt][nt][0], v1 = c[mt][nt][1];
            float v2 = c[mt][nt][2], v3 = c[mt][nt][3];
            slo += v0 * as0 + v1 * as1;  dlo += v0 * ad0 + v1 * ad1;
            shi += v2 * as0 + v3 * as1;  dhi += v2 * ad0 + v3 * ad1;
            int wcol = cb >> 1;                        // 0..31
            __half2 hlo = __floats2half2_rn(v0, v1);
            __half2 hhi = __floats2half2_rn(v2, v3);
            stg[rlo_l * 32 + (wcol ^ sw)] = *(uint32_t*)&hlo;
            stg[rhi_l * 32 + (wcol ^ sw)] = *(uint32_t*)&hhi;
        }
        #pragma unroll
        for (int o = 1; o <= 2; o <<= 1) {
            slo += __shfl_xor_sync(0xffffffffu, slo, o);
            shi += __shfl_xor_sync(0xffffffffu, shi, o);
            dlo += __shfl_xor_sync(0xffffffffu, dlo, o);
            dhi += __shfl_xor_sync(0xffffffffu, dhi, o);
        }
        if (quad == 0) {
            s_part[nw][rlo_l] = slo;  d_part[nw][rlo_l] = dlo;
            s_part[nw][rhi_l] = shi;  d_part[nw][rhi_l] = dhi;
        }
    }
    __syncthreads();
    #pragma unroll
    for (int i = 0; i < 4; i++) {
        int q = tid + 128 * i;                         // 512 uint4
        int row = q >> 3, w4 = q & 7;
        int grow = row0 + row;
        uint4 v = *(uint4*)&stg[row * 32 + ((4 * w4) ^ ((row & 7) << 2))];
        if (grow < NN) *(uint4*)(g_h2h + grow * C2 + 8 * w4) = v;
    }
    if (tid < MB) {
        int row = row0 + tid;
        if (row < NN) {
            g_as2[row] = (s_part[0][tid] + s_part[1][tid]) * LOG2E;
            g_ad2[row] = (d_part[0][tid] + d_part[1][tid]) * LOG2E;
        }
    }
}

// ---------------- conv2 aggregation: 2 edges/warp, 2 pairs in flight ----------------
__global__ void k_agg2(const float* __restrict__ b2) {
    int gw = (blockIdx.x * blockDim.x + threadIdx.x) >> 5;
    if (gw >= NN) return;
    int lane = threadIdx.x & 31;
    int half = lane >> 4, l16 = lane & 15;
    int colbase = l16 * 4;
    float ad = g_ad2[gw];
    int beg = g_rs[gw], end = g_rs[gw + 1];

    float sum = 0.f;
    float acc[4];
    #pragma unroll
    for (int i = 0; i < 4; i++) acc[i] = 0.f;

    int j = beg;
    for (; j + 4 <= end; j += 4) {                     // 2 independent pairs in flight
        int sA = g_csr[j + half];
        int sB = g_csr[j + 2 + half];
        float aA = g_as2[sA];
        float aB = g_as2[sB];
        uint2 uA = *(const uint2*)(g_h2h + sA * C2 + colbase);
        uint2 uB = *(const uint2*)(g_h2h + sB * C2 + colbase);
        float eA = ex2(lrelu(aA + ad));
        float eB = ex2(lrelu(aB + ad));
        sum += eA + eB;
        float2 fA0 = __half22float2(*(__half2*)&uA.x), fA1 = __half22float2(*(__half2*)&uA.y);
        float2 fB0 = __half22float2(*(__half2*)&uB.x), fB1 = __half22float2(*(__half2*)&uB.y);
        acc[0] += eA * fA0.x + eB * fB0.x; acc[1] += eA * fA0.y + eB * fB0.y;
        acc[2] += eA * fA1.x + eB * fB1.x; acc[3] += eA * fA1.y + eB * fB1.y;
    }
    for (; j + 2 <= end; j += 2) {
        int s = g_csr[j + half];
        float a = g_as2[s];
        uint2 u = *(const uint2*)(g_h2h + s * C2 + colbase);
        float e = ex2(lrelu(a + ad));
        sum += e;
        float2 f0 = __half22float2(*(__half2*)&u.x);
        float2 f1 = __half22float2(*(__half2*)&u.y);
        acc[0] += e * f0.x; acc[1] += e * f0.y;
        acc[2] += e * f1.x; acc[3] += e * f1.y;
    }
    if (j < end && half == 0) {
        int s = g_csr[j];
        float a = g_as2[s];
        uint2 u = *(const uint2*)(g_h2h + s * C2 + colbase);
        float e = ex2(lrelu(a + ad));
        sum += e;
        float2 f0 = __half22float2(*(__half2*)&u.x);
        float2 f1 = __half22float2(*(__half2*)&u.y);
        acc[0] += e * f0.x; acc[1] += e * f0.y;
        acc[2] += e * f1.x; acc[3] += e * f1.y;
    }
    sum += __shfl_xor_sync(0xffffffffu, sum, 16);
    #pragma unroll
    for (int i = 0; i < 4; i++) acc[i] += __shfl_xor_sync(0xffffffffu, acc[i], 16);

    if (half == 0) {
        float inv = 1.0f / (sum + 1e-16f);
        float4 bv = *(const float4*)(b2 + colbase);
        __half2 o0 = __floats2half2_rn(elu1(acc[0] * inv + bv.x), elu1(acc[1] * inv + bv.y));
        __half2 o1 = __floats2half2_rn(elu1(acc[2] * inv + bv.z), elu1(acc[3] * inv + bv.w));
        uint2 o = make_uint2(*(unsigned*)&o0, *(unsigned*)&o1);
        *(uint2*)(g_out2h + gw * C2 + colbase) = o;
    }
}

// ---------------- fused global mean pool + classifier (1 block per graph) ----------------
__global__ void __launch_bounds__(256) k_poolfinal(
        const int* __restrict__ batch, const float* __restrict__ Wc,
        const float* __restrict__ bc, float* __restrict__ out) {
    __shared__ int sb[2];
    __shared__ float red[4][C2];
    __shared__ float pooled[C2];
    int g = blockIdx.x, tid = threadIdx.x;
    if (tid < 2) {
        int target = g + tid;
        int lo = 0, hi = NN;
        while (lo < hi) { int mid = (lo + hi) >> 1; if (batch[mid] < target) lo = mid + 1; else hi = mid; }
        sb[tid] = lo;
    }
    __syncthreads();
    int lo = sb[0], hi = sb[1];
    int ch = tid & 63, grp = tid >> 6;
    float a0 = 0.f, a1 = 0.f;
    int n = lo + grp;
    for (; n + 4 < hi; n += 8) {
        a0 += __half2float(g_out2h[n * C2 + ch]);
        a1 += __half2float(g_out2h[(n + 4) * C2 + ch]);
    }
    if (n < hi) a0 += __half2float(g_out2h[n * C2 + ch]);
    red[grp][ch] = a0 + a1;
    __syncthreads();
    if (tid < C2) {
        float cnt = (float)(hi - lo); if (cnt < 1.f) cnt = 1.f;
        pooled[tid] = (red[0][tid] + red[1][tid] + red[2][tid] + red[3][tid]) / cnt;
    }
    __syncthreads();
    if (tid < NCLS) {
        float s = 0.f;
        #pragma unroll
        for (int c2 = 0; c2 < C2; c2++) s += pooled[c2] * Wc[c2 * NCLS + tid];
        out[g * NCLS + tid] = s + bc[tid];
    }
}

// ---------------- launch ----------------
extern "C" void kernel_launch(void* const* d_in, const int* in_sizes, int n_in,
                              void* d_out, int out_size) {
    const float* x     = (const float*)d_in[0];
    const int*   ei    = (const int*)  d_in[1];   // [2, E] row-major
    const int*   batch = (const int*)  d_in[2];
    const float* W1    = (const float*)d_in[3];
    const float* atts1 = (const float*)d_in[4];
    const float* attd1 = (const float*)d_in[5];
    const float* b1    = (const float*)d_in[6];
    const float* W2    = (const float*)d_in[7];
    const float* atts2 = (const float*)d_in[8];
    const float* attd2 = (const float*)d_in[9];
    const float* b2    = (const float*)d_in[10];
    const float* Wc    = (const float*)d_in[11];
    const float* bc    = (const float*)d_in[12];
    float* out = (float*)d_out;

    int gemm_grid = (NN + MB - 1) / MB;   // 1563

    k_hist     <<<(EE / 8 + 255) / 256, 256>>>(ei + EE);
    k_scanA    <<<NCHUNK, 256>>>();
    k_scanC    <<<(NN + 511) / 512, 512>>>();
    k_scatter  <<<(SCAT_E8 + NN + 255) / 256, 256>>>(ei);
    k_prepW    <<<(3072 + 255) / 256, 256>>>(W1, W2);
    k_gemm1    <<<gemm_grid, 256>>>(x, atts1, attd1);
    k_agg1     <<<(NN * 32 + 255) / 256, 256>>>(b1);
    k_gemm2    <<<gemm_grid, 128>>>(atts2, attd2);
    k_agg2     <<<(NN * 32 + 255) / 256, 256>>>(b2);
    k_poolfinal<<<NGRAPH, 256>>>(batch, Wc, bc, out);
}

// round 14
// speedup vs baseline: 1.0196x; 1.0196x over previous
#include <cuda_runtime.h>
#include <cuda_fp16.h>
#include <math.h>
#include <stdint.h>

#define NN      100000
#define EE      1600000
#define NETOT   (EE + NN)           // edges + self loops
#define INC     128
#define C1      128                 // heads(4) * hid(32)
#define C2      64
#define HEADS   4
#define NGRAPH  64
#define NCLS    2
#define NCHUNK  ((NN + 255) / 256)  // 391
#define MB      64                  // gemm rows per block
#define SCAT_E4 (EE / 4)            // 400000 (exact)
#define LOG2E   1.44269504f

// ---------------- scratch (static __device__, no allocations) ----------------
__device__ int    g_deg[NN];        // zero at entry (BSS-zero; re-zeroed by scanC each call)
__device__ int    g_rs[NN + 1];
__device__ int    g_epos[EE];       // per-edge slot within its dst segment
__device__ int    g_csr[NETOT];
__device__ int    g_csum[512];
__device__ __align__(16) __half g_h1h[NN * C1];
__device__ float  g_as1[NN * HEADS];   // pre-scaled by log2(e)
__device__ float  g_ad1[NN * HEADS];   // pre-scaled by log2(e)
__device__ __align__(16) __half g_x2h[NN * C1];
__device__ __align__(16) __half g_h2h[NN * C2];
__device__ float  g_as2[NN];           // pre-scaled by log2(e)
__device__ float  g_ad2[NN];           // pre-scaled by log2(e)
__device__ __align__(16) __half g_out2h[NN * C2];
__device__ __align__(16) __half g_w1t[C1 * INC];   // W1^T fp16, ldsm-swizzled
__device__ __align__(16) __half g_w2t[C2 * C1];    // W2^T fp16, ldsm-swizzled

__device__ __forceinline__ float lrelu(float x) { return x > 0.f ? x : 0.2f * x; }
__device__ __forceinline__ float elu1(float x)  { return x > 0.f ? x : expm1f(x); }
__device__ __forceinline__ float ex2(float x) {
    float r;
    asm("ex2.approx.ftz.f32 %0, %1;" : "=f"(r) : "f"(x));
    return r;
}

__device__ __forceinline__ void ldsm4(uint32_t& r0, uint32_t& r1, uint32_t& r2, uint32_t& r3,
                                      uint32_t addr) {
    asm volatile("ldmatrix.sync.aligned.m8n8.x4.shared.b16 {%0,%1,%2,%3}, [%4];"
                 : "=r"(r0), "=r"(r1), "=r"(r2), "=r"(r3) : "r"(addr));
}
__device__ __forceinline__ void mma16816(float* c, const uint32_t* a, uint32_t b0, uint32_t b1) {
    asm volatile("mma.sync.aligned.m16n8k16.row.col.f32.f16.f16.f32 "
                 "{%0,%1,%2,%3},{%4,%5,%6,%7},{%8,%9},{%0,%1,%2,%3};"
                 : "+f"(c[0]), "+f"(c[1]), "+f"(c[2]), "+f"(c[3])
                 : "r"(a[0]), "r"(a[1]), "r"(a[2]), "r"(a[3]), "r"(b0), "r"(b1));
}

// ---------------- CSR build (round-12 versions: 4 edges/thread) ----------------
__global__ void k_hist(const int* __restrict__ dst) {
    int e4 = blockIdx.x * blockDim.x + threadIdx.x;
    int e = e4 * 4;
    if (e + 3 < EE) {
        int4 d = *(const int4*)(dst + e);
        int4 p;
        p.x = atomicAdd(&g_deg[d.x], 1);
        p.y = atomicAdd(&g_deg[d.y], 1);
        p.z = atomicAdd(&g_deg[d.z], 1);
        p.w = atomicAdd(&g_deg[d.w], 1);
        *(int4*)(g_epos + e) = p;
    } else {
        for (; e < EE; e++) g_epos[e] = atomicAdd(&g_deg[dst[e]], 1);
    }
}

__global__ void k_scanA() {
    __shared__ int sh[256];
    int i = blockIdx.x * 256 + threadIdx.x;
    int v = (i < NN) ? (g_deg[i] + 1) : 0;    // +1 = self loop
    sh[threadIdx.x] = v;
    __syncthreads();
    #pragma unroll
    for (int off = 1; off < 256; off <<= 1) {
        int t = (threadIdx.x >= off) ? sh[threadIdx.x - off] : 0;
        __syncthreads();
        sh[threadIdx.x] += t;
        __syncthreads();
    }
    if (i < NN) g_rs[i] = sh[threadIdx.x] - v;     // chunk-local exclusive
    if (threadIdx.x == 255) g_csum[blockIdx.x] = sh[255];
}

__global__ void __launch_bounds__(512) k_scanC() {
    __shared__ int sh[512];
    int t = threadIdx.x;
    int v = (t < NCHUNK) ? g_csum[t] : 0;
    sh[t] = v;
    __syncthreads();
    #pragma unroll
    for (int off = 1; off < 512; off <<= 1) {
        int tv = (t >= off) ? sh[t - off] : 0;
        __syncthreads();
        sh[t] += tv;
        __syncthreads();
    }
    sh[t] -= v;                                    // exclusive
    __syncthreads();
    int i = blockIdx.x * 512 + t;
    if (i < NN) {
        g_rs[i] += sh[i >> 8];
        g_deg[i] = 0;                              // reset for next invocation
    }
    if (i == 0) g_rs[NN] = NETOT;
}

__global__ void k_scatter(const int* __restrict__ ei) {
    int idx = blockIdx.x * blockDim.x + threadIdx.x;
    if (idx < SCAT_E4) {
        int e = idx * 4;
        int4 s = *(const int4*)(ei + e);
        int4 d = *(const int4*)(ei + EE + e);
        int4 p = *(const int4*)(g_epos + e);
        g_csr[g_rs[d.x] + p.x] = s.x;
        g_csr[g_rs[d.y] + p.y] = s.y;
        g_csr[g_rs[d.z] + p.z] = s.z;
        g_csr[g_rs[d.w] + p.w] = s.w;
    } else {
        int n = idx - SCAT_E4;
        if (n < NN) g_csr[g_rs[n + 1] - 1] = n;    // self loop
    }
}

// one-time weight transpose + fp16 + ldsm swizzle bake
__global__ void k_prepW(const float* __restrict__ W1, const float* __restrict__ W2) {
    int idx = blockIdx.x * blockDim.x + threadIdx.x;
    if (idx < 128 * 16) {
        int n = idx >> 4, kc = idx & 15;
        int sc = kc ^ (n & 7);
        #pragma unroll
        for (int j = 0; j < 8; j++)
            g_w1t[n * 128 + (sc << 3) + j] = __float2half(W1[(kc * 8 + j) * C1 + n]);
    } else if (idx < 128 * 16 + 64 * 16) {
        int q = idx - 128 * 16;
        int n = q >> 4, kc = q & 15;
        int sc = kc ^ (n & 7);
        #pragma unroll
        for (int j = 0; j < 8; j++)
            g_w2t[n * 128 + (sc << 3) + j] = __float2half(W2[(kc * 8 + j) * C2 + n]);
    }
}

// ---------------- GEMM1 (HMMA): h1 = x @ W1, fp16 out + attention scalars ----------------
__global__ void __launch_bounds__(256) k_gemm1(
        const float* __restrict__ x,
        const float* __restrict__ att_s, const float* __restrict__ att_d) {
    __shared__ __align__(16) __half xs[MB * 128];     // 16KB; reused as stage buffer
    __shared__ __align__(16) __half ws[128 * 128];    // 32KB
    int tid = threadIdx.x;
    int row0 = blockIdx.x * MB;

    {
        const uint4* wsrc = (const uint4*)g_w1t;
        uint4* wdst = (uint4*)ws;
        #pragma unroll
        for (int i = 0; i < 8; i++) wdst[tid + 256 * i] = wsrc[tid + 256 * i];
    }
    #pragma unroll
    for (int i = 0; i < 4; i++) {
        int idx = tid + 256 * i;
        int m = idx >> 4, cc = idx & 15;
        int gm = row0 + m; if (gm > NN - 1) gm = NN - 1;
        const float4* xp = (const float4*)(x + gm * INC + cc * 8);
        float4 v0 = xp[0], v1 = xp[1];
        __half2 h0 = __floats2half2_rn(v0.x, v0.y);
        __half2 h1 = __floats2half2_rn(v0.z, v0.w);
        __half2 h2 = __floats2half2_rn(v1.x, v1.y);
        __half2 h3 = __floats2half2_rn(v1.z, v1.w);
        uint4 pk = make_uint4(*(unsigned*)&h0, *(unsigned*)&h1, *(unsigned*)&h2, *(unsigned*)&h3);
        int sc = cc ^ (m & 7);
        *(uint4*)(xs + m * 128 + sc * 8) = pk;
    }
    __syncthreads();

    int w = tid >> 5, lane = tid & 31;
    int mw = w >> 2, nw = w & 3;
    int i8 = lane >> 3, r8 = lane & 7;
    uint32_t xbase = (uint32_t)__cvta_generic_to_shared(xs);
    uint32_t wbase = (uint32_t)__cvta_generic_to_shared(ws);

    int rowA[2], rowB[2];
    #pragma unroll
    for (int mt = 0; mt < 2; mt++) rowA[mt] = mw * 32 + mt * 16 + (i8 & 1) * 8 + r8;
    #pragma unroll
    for (int p = 0; p < 2; p++)   rowB[p] = nw * 32 + p * 16 + (i8 >> 1) * 8 + r8;
    int kcA_off = (i8 >> 1);
    int kcB_off = (i8 & 1);

    float c[2][4][4];
    #pragma unroll
    for (int mt = 0; mt < 2; mt++)
        #pragma unroll
        for (int nt = 0; nt < 4; nt++)
            #pragma unroll
            for (int q = 0; q < 4; q++) c[mt][nt][q] = 0.f;

    #pragma unroll
    for (int kt = 0; kt < 8; kt++) {
        uint32_t A[2][4], B[2][4];
        #pragma unroll
        for (int mt = 0; mt < 2; mt++) {
            int kc = kt * 2 + kcA_off;
            uint32_t addr = xbase + rowA[mt] * 256 + (((kc ^ (rowA[mt] & 7))) << 4);
            ldsm4(A[mt][0], A[mt][1], A[mt][2], A[mt][3], addr);
        }
        #pragma unroll
        for (int p = 0; p < 2; p++) {
            int kc = kt * 2 + kcB_off;
            uint32_t addr = wbase + rowB[p] * 256 + (((kc ^ (rowB[p] & 7))) << 4);
            ldsm4(B[p][0], B[p][1], B[p][2], B[p][3], addr);
        }
        #pragma unroll
        for (int mt = 0; mt < 2; mt++) {
            mma16816(c[mt][0], A[mt], B[0][0], B[0][1]);
            mma16816(c[mt][1], A[mt], B[0][2], B[0][3]);
            mma16816(c[mt][2], A[mt], B[1][0], B[1][1]);
            mma16816(c[mt][3], A[mt], B[1][2], B[1][3]);
        }
    }
    __syncthreads();                                   // xs reads done; reuse as stage

    uint32_t* stg = (uint32_t*)xs;                     // 64 rows x 64 words
    int quad = lane & 3;
    #pragma unroll
    for (int mt = 0; mt < 2; mt++) {
        int rlo_l = mw * 32 + mt * 16 + (lane >> 2);
        int rhi_l = rlo_l + 8;
        int rlo = row0 + rlo_l, rhi = row0 + rhi_l;
        int sw = (rlo_l & 7) << 2;                     // same for rhi_l
        float slo = 0.f, shi = 0.f, dlo = 0.f, dhi = 0.f;
        #pragma unroll
        for (int nt = 0; nt < 4; nt++) {
            int cb = nw * 32 + nt * 8 + 2 * quad;
            float as0 = att_s[cb], as1 = att_s[cb + 1];
            float ad0 = att_d[cb], ad1 = att_d[cb + 1];
            float v0 = c[mt][nt][0], v1 = c[mt][nt][1];
            float v2 = c[mt][nt][2], v3 = c[mt][nt][3];
            slo += v0 * as0 + v1 * as1;  dlo += v0 * ad0 + v1 * ad1;
            shi += v2 * as0 + v3 * as1;  dhi += v2 * ad0 + v3 * ad1;
            int wcol = cb >> 1;
            __half2 hlo = __floats2half2_rn(v0, v1);
            __half2 hhi = __floats2half2_rn(v2, v3);
            stg[rlo_l * 64 + (wcol ^ sw)] = *(uint32_t*)&hlo;
            stg[rhi_l * 64 + (wcol ^ sw)] = *(uint32_t*)&hhi;
        }
        #pragma unroll
        for (int o = 1; o <= 2; o <<= 1) {
            slo += __shfl_xor_sync(0xffffffffu, slo, o);
            shi += __shfl_xor_sync(0xffffffffu, shi, o);
            dlo += __shfl_xor_sync(0xffffffffu, dlo, o);
            dhi += __shfl_xor_sync(0xffffffffu, dhi, o);
        }
        if (quad == 0) {
            if (rlo < NN) { g_as1[rlo * 4 + nw] = slo * LOG2E; g_ad1[rlo * 4 + nw] = dlo * LOG2E; }
            if (rhi < NN) { g_as1[rhi * 4 + nw] = shi * LOG2E; g_ad1[rhi * 4 + nw] = dhi * LOG2E; }
        }
    }
    __syncthreads();
    #pragma unroll
    for (int i = 0; i < 4; i++) {
        int q = tid + 256 * i;                         // 1024 uint4
        int row = q >> 4, w4 = q & 15;
        int grow = row0 + row;
        uint4 v = *(uint4*)&stg[row * 64 + ((4 * w4) ^ ((row & 7) << 2))];
        if (grow < NN) *(uint4*)(g_h1h + grow * C1 + 8 * w4) = v;
    }
}

// ---- conv1 aggregation: 2 edges/warp, fp16 inner accumulation (flush every 8 edges) ----
__global__ void k_agg1(const float* __restrict__ b1) {
    int gw = (blockIdx.x * blockDim.x + threadIdx.x) >> 5;
    if (gw >= NN) return;
    int lane = threadIdx.x & 31;
    int half = lane >> 4, l16 = lane & 15;
    int colbase = l16 * 8;
    int head = l16 >> 2;
    float adh = g_ad1[gw * 4 + head];
    int beg = g_rs[gw], end = g_rs[gw + 1];

    float sum = 0.f;
    float acc[8];
    #pragma unroll
    for (int i = 0; i < 8; i++) acc[i] = 0.f;

    int j = beg;
    for (; j + 8 <= end; j += 8) {                     // 8-edge block: fp16 partials
        __half2 ah0 = __float2half2_rn(0.f), ah1 = ah0, ah2 = ah0, ah3 = ah0;
        #pragma unroll
        for (int q = 0; q < 4; q++) {
            int s = g_csr[j + 2 * q + half];
            float a = g_as1[s * 4 + head];
            uint4 u = *(const uint4*)(g_h1h + s * C1 + colbase);
            float e = ex2(lrelu(a + adh));
            sum += e;
            __half2 eh = __float2half2_rn(e);
            ah0 = __hfma2(eh, *(__half2*)&u.x, ah0);
            ah1 = __hfma2(eh, *(__half2*)&u.y, ah1);
            ah2 = __hfma2(eh, *(__half2*)&u.z, ah2);
            ah3 = __hfma2(eh, *(__half2*)&u.w, ah3);
        }
        float2 t0 = __half22float2(ah0), t1 = __half22float2(ah1);
        float2 t2 = __half22float2(ah2), t3 = __half22float2(ah3);
        acc[0] += t0.x; acc[1] += t0.y; acc[2] += t1.x; acc[3] += t1.y;
        acc[4] += t2.x; acc[5] += t2.y; acc[6] += t3.x; acc[7] += t3.y;
    }
    for (; j + 2 <= end; j += 2) {                     // tail pairs: fp32 path
        int s = g_csr[j + half];
        float a = g_as1[s * 4 + head];
        uint4 u = *(const uint4*)(g_h1h + s * C1 + colbase);
        float e = ex2(lrelu(a + adh));
        sum += e;
        float2 f0 = __half22float2(*(__half2*)&u.x);
        float2 f1 = __half22float2(*(__half2*)&u.y);
        float2 f2 = __half22float2(*(__half2*)&u.z);
        float2 f3 = __half22float2(*(__half2*)&u.w);
        acc[0] += e * f0.x; acc[1] += e * f0.y;
        acc[2] += e * f1.x; acc[3] += e * f1.y;
        acc[4] += e * f2.x; acc[5] += e * f2.y;
        acc[6] += e * f3.x; acc[7] += e * f3.y;
    }
    if (j < end && half == 0) {                        // odd tail: A-half only
        int s = g_csr[j];
        float a = g_as1[s * 4 + head];
        uint4 u = *(const uint4*)(g_h1h + s * C1 + colbase);
        float e = ex2(lrelu(a + adh));
        sum += e;
        float2 f0 = __half22float2(*(__half2*)&u.x);
        float2 f1 = __half22float2(*(__half2*)&u.y);
        float2 f2 = __half22float2(*(__half2*)&u.z);
        float2 f3 = __half22float2(*(__half2*)&u.w);
        acc[0] += e * f0.x; acc[1] += e * f0.y;
        acc[2] += e * f1.x; acc[3] += e * f1.y;
        acc[4] += e * f2.x; acc[5] += e * f2.y;
        acc[6] += e * f3.x; acc[7] += e * f3.y;
    }
    // merge the two halves
    sum += __shfl_xor_sync(0xffffffffu, sum, 16);
    #pragma unroll
    for (int i = 0; i < 8; i++) acc[i] += __shfl_xor_sync(0xffffffffu, acc[i], 16);

    if (half == 0) {
        float inv = 1.0f / (sum + 1e-16f);
        float4 bva = *(const float4*)(b1 + colbase);
        float4 bvb = *(const float4*)(b1 + colbase + 4);
        __half2 o0 = __floats2half2_rn(elu1(acc[0] * inv + bva.x), elu1(acc[1] * inv + bva.y));
        __half2 o1 = __floats2half2_rn(elu1(acc[2] * inv + bva.z), elu1(acc[3] * inv + bva.w));
        __half2 o2 = __floats2half2_rn(elu1(acc[4] * inv + bvb.x), elu1(acc[5] * inv + bvb.y));
        __half2 o3 = __floats2half2_rn(elu1(acc[6] * inv + bvb.z), elu1(acc[7] * inv + bvb.w));
        uint4 o = make_uint4(*(unsigned*)&o0, *(unsigned*)&o1, *(unsigned*)&o2, *(unsigned*)&o3);
        *(uint4*)(g_x2h + gw * C1 + colbase) = o;
    }
}

// ---------------- GEMM2 (HMMA): h2 = x2 @ W2, fp16 out + attention scalars ----------------
__global__ void __launch_bounds__(128) k_gemm2(
        const float* __restrict__ att_s, const float* __restrict__ att_d) {
    __shared__ __align__(16) __half xs[MB * 128];    // 16KB; reused as stage
    __shared__ __align__(16) __half ws[C2 * 128];    // 16KB
    __shared__ float s_part[2][MB], d_part[2][MB];
    int tid = threadIdx.x;
    int row0 = blockIdx.x * MB;

    {
        const uint4* wsrc = (const uint4*)g_w2t;
        uint4* wdst = (uint4*)ws;
        #pragma unroll
        for (int i = 0; i < 8; i++) wdst[tid + 128 * i] = wsrc[tid + 128 * i];
    }
    #pragma unroll
    for (int i = 0; i < 8; i++) {
        int idx = tid + 128 * i;
        int m = idx >> 4, cc = idx & 15;
        int gm = row0 + m; if (gm > NN - 1) gm = NN - 1;
        uint4 pk = *(const uint4*)(g_x2h + gm * C1 + cc * 8);
        int sc = cc ^ (m & 7);
        *(uint4*)(xs + m * 128 + sc * 8) = pk;
    }
    __syncthreads();

    int w = tid >> 5, lane = tid & 31;
    int mw = w >> 1, nw = w & 1;
    int i8 = lane >> 3, r8 = lane & 7;
    uint32_t xbase = (uint32_t)__cvta_generic_to_shared(xs);
    uint32_t wbase = (uint32_t)__cvta_generic_to_shared(ws);

    int rowA[2], rowB[2];
    #pragma unroll
    for (int mt = 0; mt < 2; mt++) rowA[mt] = mw * 32 + mt * 16 + (i8 & 1) * 8 + r8;
    #pragma unroll
    for (int p = 0; p < 2; p++)   rowB[p] = nw * 32 + p * 16 + (i8 >> 1) * 8 + r8;
    int kcA_off = (i8 >> 1), kcB_off = (i8 & 1);

    float c[2][4][4];
    #pragma unroll
    for (int mt = 0; mt < 2; mt++)
        #pragma unroll
        for (int nt = 0; nt < 4; nt++)
            #pragma unroll
            for (int q = 0; q < 4; q++) c[mt][nt][q] = 0.f;

    #pragma unroll
    for (int kt = 0; kt < 8; kt++) {
        uint32_t A[2][4], B[2][4];
        #pragma unroll
        for (int mt = 0; mt < 2; mt++) {
            int kc = kt * 2 + kcA_off;
            uint32_t addr = xbase + rowA[mt] * 256 + (((kc ^ (rowA[mt] & 7))) << 4);
            ldsm4(A[mt][0], A[mt][1], A[mt][2], A[mt][3], addr);
        }
        #pragma unroll
        for (int p = 0; p < 2; p++) {
            int kc = kt * 2 + kcB_off;
            uint32_t addr = wbase + rowB[p] * 256 + (((kc ^ (rowB[p] & 7))) << 4);
            ldsm4(B[p][0], B[p][1], B[p][2], B[p][3], addr);
        }
        #pragma unroll
        for (int mt = 0; mt < 2; mt++) {
            mma16816(c[mt][0], A[mt], B[0][0], B[0][1]);
            mma16816(c[mt][1], A[mt], B[0][2], B[0][3]);
            mma16816(c[mt][2], A[mt], B[1][0], B[1][1]);
            mma16816(c[mt][3], A[mt], B[1][2], B[1][3]);
        }
    }
    __syncthreads();                                   // xs reads done; reuse as stage

    uint32_t* stg = (uint32_t*)xs;                     // 64 rows x 32 words
    int quad = lane & 3;
    #pragma unroll
    for (int mt = 0; mt < 2; mt++) {
        int rlo_l = mw * 32 + mt * 16 + (lane >> 2);
        int rhi_l = rlo_l + 8;
        int sw = (rlo_l & 7) << 2;
        float slo = 0.f, shi = 0.f, dlo = 0.f, dhi = 0.f;
        #pragma unroll
        for (int nt = 0; nt < 4; nt++) {
            int cb = nw * 32 + nt * 8 + 2 * quad;
            float as0 = att_s[cb], as1 = att_s[cb + 1];
            float ad0 = att_d[cb], ad1 = att_d[cb + 1];
            float v0 = c[mt][nt][0], v1 = c[mt][nt][1];
            float v2 = c[mt][nt][2], v3 = c[mt][nt][3];
            slo += v0 * as0 + v1 * as1;  dlo += v0 * ad0 + v1 * ad1;
            shi += v2 * as0 + v3 * as1;  dhi += v2 * ad0 + v3 * ad1;
            int wcol = cb >> 1;                        // 0..31
            __half2 hlo = __floats2half2_rn(v0, v1);
            __half2 hhi = __floats2half2_rn(v2, v3);
            stg[rlo_l * 32 + (wcol ^ sw)] = *(uint32_t*)&hlo;
            stg[rhi_l * 32 + (wcol ^ sw)] = *(uint32_t*)&hhi;
        }
        #pragma unroll
        for (int o = 1; o <= 2; o <<= 1) {
            slo += __shfl_xor_sync(0xffffffffu, slo, o);
            shi += __shfl_xor_sync(0xffffffffu, shi, o);
            dlo += __shfl_xor_sync(0xffffffffu, dlo, o);
            dhi += __shfl_xor_sync(0xffffffffu, dhi, o);
        }
        if (quad == 0) {
            s_part[nw][rlo_l] = slo;  d_part[nw][rlo_l] = dlo;
            s_part[nw][rhi_l] = shi;  d_part[nw][rhi_l] = dhi;
        }
    }
    __syncthreads();
    #pragma unroll
    for (int i = 0; i < 4; i++) {
        int q = tid + 128 * i;                         // 512 uint4
        int row = q >> 3, w4 = q & 7;
        int grow = row0 + row;
        uint4 v = *(uint4*)&stg[row * 32 + ((4 * w4) ^ ((row & 7) << 2))];
        if (grow < NN) *(uint4*)(g_h2h + grow * C2 + 8 * w4) = v;
    }
    if (tid < MB) {
        int row = row0 + tid;
        if (row < NN) {
            g_as2[row] = (s_part[0][tid] + s_part[1][tid]) * LOG2E;
            g_ad2[row] = (d_part[0][tid] + d_part[1][tid]) * LOG2E;
        }
    }
}

// ---- conv2 aggregation: 2 edges/warp, fp16 inner accumulation (flush every 8 edges) ----
__global__ void k_agg2(const float* __restrict__ b2) {
    int gw = (blockIdx.x * blockDim.x + threadIdx.x) >> 5;
    if (gw >= NN) return;
    int lane = threadIdx.x & 31;
    int half = lane >> 4, l16 = lane & 15;
    int colbase = l16 * 4;
    float ad = g_ad2[gw];
    int beg = g_rs[gw], end = g_rs[gw + 1];

    float sum = 0.f;
    float acc[4];
    #pragma unroll
    for (int i = 0; i < 4; i++) acc[i] = 0.f;

    int j = beg;
    for (; j + 8 <= end; j += 8) {                     // 8-edge block: fp16 partials
        __half2 ah0 = __float2half2_rn(0.f), ah1 = ah0;
        #pragma unroll
        for (int q = 0; q < 4; q++) {
            int s = g_csr[j + 2 * q + half];
            float a = g_as2[s];
            uint2 u = *(const uint2*)(g_h2h + s * C2 + colbase);
            float e = ex2(lrelu(a + ad));
            sum += e;
            __half2 eh = __float2half2_rn(e);
            ah0 = __hfma2(eh, *(__half2*)&u.x, ah0);
            ah1 = __hfma2(eh, *(__half2*)&u.y, ah1);
        }
        float2 t0 = __half22float2(ah0), t1 = __half22float2(ah1);
        acc[0] += t0.x; acc[1] += t0.y; acc[2] += t1.x; acc[3] += t1.y;
    }
    for (; j + 2 <= end; j += 2) {                     // tail pairs: fp32 path
        int s = g_csr[j + half];
        float a = g_as2[s];
        uint2 u = *(const uint2*)(g_h2h + s * C2 + colbase);
        float e = ex2(lrelu(a + ad));
        sum += e;
        float2 f0 = __half22float2(*(__half2*)&u.x);
        float2 f1 = __half22float2(*(__half2*)&u.y);
        acc[0] += e * f0.x; acc[1] += e * f0.y;
        acc[2] += e * f1.x; acc[3] += e * f1.y;
    }
    if (j < end && half == 0) {
        int s = g_csr[j];
        float a = g_as2[s];
        uint2 u = *(const uint2*)(g_h2h + s * C2 + colbase);
        float e = ex2(lrelu(a + ad));
        sum += e;
        float2 f0 = __half22float2(*(__half2*)&u.x);
        float2 f1 = __half22float2(*(__half2*)&u.y);
        acc[0] += e * f0.x; acc[1] += e * f0.y;
        acc[2] += e * f1.x; acc[3] += e * f1.y;
    }
    sum += __shfl_xor_sync(0xffffffffu, sum, 16);
    #pragma unroll
    for (int i = 0; i < 4; i++) acc[i] += __shfl_xor_sync(0xffffffffu, acc[i], 16);

    if (half == 0) {
        float inv = 1.0f / (sum + 1e-16f);
        float4 bv = *(const float4*)(b2 + colbase);
        __half2 o0 = __floats2half2_rn(elu1(acc[0] * inv + bv.x), elu1(acc[1] * inv + bv.y));
        __half2 o1 = __floats2half2_rn(elu1(acc[2] * inv + bv.z), elu1(acc[3] * inv + bv.w));
        uint2 o = make_uint2(*(unsigned*)&o0, *(unsigned*)&o1);
        *(uint2*)(g_out2h + gw * C2 + colbase) = o;
    }
}

// ---------------- fused global mean pool + classifier (1 block per graph) ----------------
__global__ void __launch_bounds__(256) k_poolfinal(
        const int* __restrict__ batch, const float* __restrict__ Wc,
        const float* __restrict__ bc, float* __restrict__ out) {
    __shared__ int sb[2];
    __shared__ float red[4][C2];
    __shared__ float pooled[C2];
    int g = blockIdx.x, tid = threadIdx.x;
    if (tid < 2) {
        int target = g + tid;
        int lo = 0, hi = NN;
        while (lo < hi) { int mid = (lo + hi) >> 1; if (batch[mid] < target) lo = mid + 1; else hi = mid; }
        sb[tid] = lo;
    }
    __syncthreads();
    int lo = sb[0], hi = sb[1];
    int ch = tid & 63, grp = tid >> 6;
    float a0 = 0.f, a1 = 0.f;
    int n = lo + grp;
    for (; n + 4 < hi; n += 8) {
        a0 += __half2float(g_out2h[n * C2 + ch]);
        a1 += __half2float(g_out2h[(n + 4) * C2 + ch]);
    }
    if (n < hi) a0 += __half2float(g_out2h[n * C2 + ch]);
    red[grp][ch] = a0 + a1;
    __syncthreads();
    if (tid < C2) {
        float cnt = (float)(hi - lo); if (cnt < 1.f) cnt = 1.f;
        pooled[tid] = (red[0][tid] + red[1][tid] + red[2][tid] + red[3][tid]) / cnt;
    }
    __syncthreads();
    if (tid < NCLS) {
        float s = 0.f;
        #pragma unroll
        for (int c2 = 0; c2 < C2; c2++) s += pooled[c2] * Wc[c2 * NCLS + tid];
        out[g * NCLS + tid] = s + bc[tid];
    }
}

// ---------------- launch ----------------
extern "C" void kernel_launch(void* const* d_in, const int* in_sizes, int n_in,
                              void* d_out, int out_size) {
    const float* x     = (const float*)d_in[0];
    const int*   ei    = (const int*)  d_in[1];   // [2, E] row-major
    const int*   batch = (const int*)  d_in[2];
    const float* W1    = (const float*)d_in[3];
    const float* atts1 = (const float*)d_in[4];
    const float* attd1 = (const float*)d_in[5];
    const float* b1    = (const float*)d_in[6];
    const float* W2    = (const float*)d_in[7];
    const float* atts2 = (const float*)d_in[8];
    const float* attd2 = (const float*)d_in[9];
    const float* b2    = (const float*)d_in[10];
    const float* Wc    = (const float*)d_in[11];
    const float* bc    = (const float*)d_in[12];
    float* out = (float*)d_out;

    int gemm_grid = (NN + MB - 1) / MB;   // 1563

    k_hist     <<<(EE / 4 + 255) / 256, 256>>>(ei + EE);
    k_scanA    <<<NCHUNK, 256>>>();
    k_scanC    <<<(NN + 511) / 512, 512>>>();
    k_scatter  <<<(SCAT_E4 + NN + 255) / 256, 256>>>(ei);
    k_prepW    <<<(3072 + 255) / 256, 256>>>(W1, W2);
    k_gemm1    <<<gemm_grid, 256>>>(x, atts1, attd1);
    k_agg1     <<<(NN * 32 + 255) / 256, 256>>>(b1);
    k_gemm2    <<<gemm_grid, 128>>>(atts2, attd2);
    k_agg2     <<<(NN * 32 + 255) / 256, 256>>>(b2);
    k_poolfinal<<<NGRAPH, 256>>>(batch, Wc, bc, out);
}

// round 15
// speedup vs baseline: 1.0339x; 1.0141x over previous
#include <cuda_runtime.h>
#include <cuda_fp16.h>
#include <math.h>
#include <stdint.h>

#define NN      100000
#define EE      1600000
#define NETOT   (EE + NN)           // edges + self loops
#define INC     128
#define C1      128                 // heads(4) * hid(32)
#define C2      64
#define HEADS   4
#define NGRAPH  64
#define NCLS    2
#define NCHUNK  ((NN + 255) / 256)  // 391
#define MB      64                  // gemm rows per block
#define SCAT_E4 (EE / 4)            // 400000 (exact)
#define LOG2E   1.44269504f

// ---------------- scratch (static __device__, no allocations) ----------------
__device__ int    g_deg[NN];        // zero at entry (BSS-zero; re-zeroed by scanC each call)
__device__ int    g_rs[NN + 1];
__device__ int    g_epos[EE];       // per-edge slot within its dst segment
__device__ int    g_csr[NETOT];
__device__ int    g_csum[512];
__device__ __align__(16) __half g_h1h[NN * C1];
__device__ float  g_as1[NN * HEADS];   // pre-scaled by log2(e)
__device__ float  g_ad1[NN * HEADS];   // pre-scaled by log2(e)
__device__ __align__(16) __half g_x2h[NN * C1];
__device__ __align__(16) __half g_h2h[NN * C2];
__device__ float  g_as2[NN];           // pre-scaled by log2(e)
__device__ float  g_ad2[NN];           // pre-scaled by log2(e)
__device__ __align__(16) __half g_out2h[NN * C2];
__device__ __align__(16) __half g_w1t[C1 * INC];   // W1^T fp16, ldsm-swizzled
__device__ __align__(16) __half g_w2t[C2 * C1];    // W2^T fp16, ldsm-swizzled

__device__ __forceinline__ float lrelu(float x) { return x > 0.f ? x : 0.2f * x; }
__device__ __forceinline__ float elu1(float x)  { return x > 0.f ? x : expm1f(x); }
__device__ __forceinline__ float ex2(float x) {
    float r;
    asm("ex2.approx.ftz.f32 %0, %1;" : "=f"(r) : "f"(x));
    return r;
}

__device__ __forceinline__ void ldsm4(uint32_t& r0, uint32_t& r1, uint32_t& r2, uint32_t& r3,
                                      uint32_t addr) {
    asm volatile("ldmatrix.sync.aligned.m8n8.x4.shared.b16 {%0,%1,%2,%3}, [%4];"
                 : "=r"(r0), "=r"(r1), "=r"(r2), "=r"(r3) : "r"(addr));
}
__device__ __forceinline__ void mma16816(float* c, const uint32_t* a, uint32_t b0, uint32_t b1) {
    asm volatile("mma.sync.aligned.m16n8k16.row.col.f32.f16.f16.f32 "
                 "{%0,%1,%2,%3},{%4,%5,%6,%7},{%8,%9},{%0,%1,%2,%3};"
                 : "+f"(c[0]), "+f"(c[1]), "+f"(c[2]), "+f"(c[3])
                 : "r"(a[0]), "r"(a[1]), "r"(a[2]), "r"(a[3]), "r"(b0), "r"(b1));
}

// ---------------- CSR build ----------------
__global__ void k_hist(const int* __restrict__ dst) {
    int e4 = blockIdx.x * blockDim.x + threadIdx.x;
    int e = e4 * 4;
    if (e + 3 < EE) {
        int4 d = *(const int4*)(dst + e);
        int4 p;
        p.x = atomicAdd(&g_deg[d.x], 1);
        p.y = atomicAdd(&g_deg[d.y], 1);
        p.z = atomicAdd(&g_deg[d.z], 1);
        p.w = atomicAdd(&g_deg[d.w], 1);
        *(int4*)(g_epos + e) = p;
    } else {
        for (; e < EE; e++) g_epos[e] = atomicAdd(&g_deg[dst[e]], 1);
    }
}

__global__ void k_scanA() {
    __shared__ int sh[256];
    int i = blockIdx.x * 256 + threadIdx.x;
    int v = (i < NN) ? (g_deg[i] + 1) : 0;    // +1 = self loop
    sh[threadIdx.x] = v;
    __syncthreads();
    #pragma unroll
    for (int off = 1; off < 256; off <<= 1) {
        int t = (threadIdx.x >= off) ? sh[threadIdx.x - off] : 0;
        __syncthreads();
        sh[threadIdx.x] += t;
        __syncthreads();
    }
    if (i < NN) g_rs[i] = sh[threadIdx.x] - v;     // chunk-local exclusive
    if (threadIdx.x == 255) g_csum[blockIdx.x] = sh[255];
}

__global__ void __launch_bounds__(512) k_scanC() {
    __shared__ int sh[512];
    int t = threadIdx.x;
    int v = (t < NCHUNK) ? g_csum[t] : 0;
    sh[t] = v;
    __syncthreads();
    #pragma unroll
    for (int off = 1; off < 512; off <<= 1) {
        int tv = (t >= off) ? sh[t - off] : 0;
        __syncthreads();
        sh[t] += tv;
        __syncthreads();
    }
    sh[t] -= v;                                    // exclusive
    __syncthreads();
    int i = blockIdx.x * 512 + t;
    if (i < NN) {
        g_rs[i] += sh[i >> 8];
        g_deg[i] = 0;                              // reset for next invocation
    }
    if (i == 0) g_rs[NN] = NETOT;
}

__global__ void k_scatter(const int* __restrict__ ei) {
    int idx = blockIdx.x * blockDim.x + threadIdx.x;
    if (idx < SCAT_E4) {
        int e = idx * 4;
        int4 s = *(const int4*)(ei + e);
        int4 d = *(const int4*)(ei + EE + e);
        int4 p = *(const int4*)(g_epos + e);
        g_csr[g_rs[d.x] + p.x] = s.x;
        g_csr[g_rs[d.y] + p.y] = s.y;
        g_csr[g_rs[d.z] + p.z] = s.z;
        g_csr[g_rs[d.w] + p.w] = s.w;
    } else {
        int n = idx - SCAT_E4;
        if (n < NN) g_csr[g_rs[n + 1] - 1] = n;    // self loop
    }
}

// one-time weight transpose + fp16 + ldsm swizzle bake
__global__ void k_prepW(const float* __restrict__ W1, const float* __restrict__ W2) {
    int idx = blockIdx.x * blockDim.x + threadIdx.x;
    if (idx < 128 * 16) {
        int n = idx >> 4, kc = idx & 15;
        int sc = kc ^ (n & 7);
        #pragma unroll
        for (int j = 0; j < 8; j++)
            g_w1t[n * 128 + (sc << 3) + j] = __float2half(W1[(kc * 8 + j) * C1 + n]);
    } else if (idx < 128 * 16 + 64 * 16) {
        int q = idx - 128 * 16;
        int n = q >> 4, kc = q & 15;
        int sc = kc ^ (n & 7);
        #pragma unroll
        for (int j = 0; j < 8; j++)
            g_w2t[n * 128 + (sc << 3) + j] = __float2half(W2[(kc * 8 + j) * C2 + n]);
    }
}

// ---------------- GEMM1 (HMMA): h1 = x @ W1, fp16 out + attention scalars ----------------
__global__ void __launch_bounds__(256) k_gemm1(
        const float* __restrict__ x,
        const float* __restrict__ att_s, const float* __restrict__ att_d) {
    __shared__ __align__(16) __half xs[MB * 128];     // 16KB; reused as stage buffer
    __shared__ __align__(16) __half ws[128 * 128];    // 32KB
    int tid = threadIdx.x;
    int row0 = blockIdx.x * MB;

    {
        const uint4* wsrc = (const uint4*)g_w1t;
        uint4* wdst = (uint4*)ws;
        #pragma unroll
        for (int i = 0; i < 8; i++) wdst[tid + 256 * i] = wsrc[tid + 256 * i];
    }
    #pragma unroll
    for (int i = 0; i < 4; i++) {
        int idx = tid + 256 * i;
        int m = idx >> 4, cc = idx & 15;
        int gm = row0 + m; if (gm > NN - 1) gm = NN - 1;
        const float4* xp = (const float4*)(x + gm * INC + cc * 8);
        float4 v0 = xp[0], v1 = xp[1];
        __half2 h0 = __floats2half2_rn(v0.x, v0.y);
        __half2 h1 = __floats2half2_rn(v0.z, v0.w);
        __half2 h2 = __floats2half2_rn(v1.x, v1.y);
        __half2 h3 = __floats2half2_rn(v1.z, v1.w);
        uint4 pk = make_uint4(*(unsigned*)&h0, *(unsigned*)&h1, *(unsigned*)&h2, *(unsigned*)&h3);
        int sc = cc ^ (m & 7);
        *(uint4*)(xs + m * 128 + sc * 8) = pk;
    }
    __syncthreads();

    int w = tid >> 5, lane = tid & 31;
    int mw = w >> 2, nw = w & 3;
    int i8 = lane >> 3, r8 = lane & 7;
    uint32_t xbase = (uint32_t)__cvta_generic_to_shared(xs);
    uint32_t wbase = (uint32_t)__cvta_generic_to_shared(ws);

    int rowA[2], rowB[2];
    #pragma unroll
    for (int mt = 0; mt < 2; mt++) rowA[mt] = mw * 32 + mt * 16 + (i8 & 1) * 8 + r8;
    #pragma unroll
    for (int p = 0; p < 2; p++)   rowB[p] = nw * 32 + p * 16 + (i8 >> 1) * 8 + r8;
    int kcA_off = (i8 >> 1);
    int kcB_off = (i8 & 1);

    float c[2][4][4];
    #pragma unroll
    for (int mt = 0; mt < 2; mt++)
        #pragma unroll
        for (int nt = 0; nt < 4; nt++)
            #pragma unroll
            for (int q = 0; q < 4; q++) c[mt][nt][q] = 0.f;

    #pragma unroll
    for (int kt = 0; kt < 8; kt++) {
        uint32_t A[2][4], B[2][4];
        #pragma unroll
        for (int mt = 0; mt < 2; mt++) {
            int kc = kt * 2 + kcA_off;
            uint32_t addr = xbase + rowA[mt] * 256 + (((kc ^ (rowA[mt] & 7))) << 4);
            ldsm4(A[mt][0], A[mt][1], A[mt][2], A[mt][3], addr);
        }
        #pragma unroll
        for (int p = 0; p < 2; p++) {
            int kc = kt * 2 + kcB_off;
            uint32_t addr = wbase + rowB[p] * 256 + (((kc ^ (rowB[p] & 7))) << 4);
            ldsm4(B[p][0], B[p][1], B[p][2], B[p][3], addr);
        }
        #pragma unroll
        for (int mt = 0; mt < 2; mt++) {
            mma16816(c[mt][0], A[mt], B[0][0], B[0][1]);
            mma16816(c[mt][1], A[mt], B[0][2], B[0][3]);
            mma16816(c[mt][2], A[mt], B[1][0], B[1][1]);
            mma16816(c[mt][3], A[mt], B[1][2], B[1][3]);
        }
    }
    __syncthreads();                                   // xs reads done; reuse as stage

    uint32_t* stg = (uint32_t*)xs;                     // 64 rows x 64 words
    int quad = lane & 3;
    #pragma unroll
    for (int mt = 0; mt < 2; mt++) {
        int rlo_l = mw * 32 + mt * 16 + (lane >> 2);
        int rhi_l = rlo_l + 8;
        int rlo = row0 + rlo_l, rhi = row0 + rhi_l;
        int sw = (rlo_l & 7) << 2;                     // same for rhi_l
        float slo = 0.f, shi = 0.f, dlo = 0.f, dhi = 0.f;
        #pragma unroll
        for (int nt = 0; nt < 4; nt++) {
            int cb = nw * 32 + nt * 8 + 2 * quad;
            float as0 = att_s[cb], as1 = att_s[cb + 1];
            float ad0 = att_d[cb], ad1 = att_d[cb + 1];
            float v0 = c[mt][nt][0], v1 = c[mt][nt][1];
            float v2 = c[mt][nt][2], v3 = c[mt][nt][3];
            slo += v0 * as0 + v1 * as1;  dlo += v0 * ad0 + v1 * ad1;
            shi += v2 * as0 + v3 * as1;  dhi += v2 * ad0 + v3 * ad1;
            int wcol = cb >> 1;
            __half2 hlo = __floats2half2_rn(v0, v1);
            __half2 hhi = __floats2half2_rn(v2, v3);
            stg[rlo_l * 64 + (wcol ^ sw)] = *(uint32_t*)&hlo;
            stg[rhi_l * 64 + (wcol ^ sw)] = *(uint32_t*)&hhi;
        }
        #pragma unroll
        for (int o = 1; o <= 2; o <<= 1) {
            slo += __shfl_xor_sync(0xffffffffu, slo, o);
            shi += __shfl_xor_sync(0xffffffffu, shi, o);
            dlo += __shfl_xor_sync(0xffffffffu, dlo, o);
            dhi += __shfl_xor_sync(0xffffffffu, dhi, o);
        }
        if (quad == 0) {
            if (rlo < NN) { g_as1[rlo * 4 + nw] = slo * LOG2E; g_ad1[rlo * 4 + nw] = dlo * LOG2E; }
            if (rhi < NN) { g_as1[rhi * 4 + nw] = shi * LOG2E; g_ad1[rhi * 4 + nw] = dhi * LOG2E; }
        }
    }
    __syncthreads();
    #pragma unroll
    for (int i = 0; i < 4; i++) {
        int q = tid + 256 * i;                         // 1024 uint4
        int row = q >> 4, w4 = q & 15;
        int grow = row0 + row;
        uint4 v = *(uint4*)&stg[row * 64 + ((4 * w4) ^ ((row & 7) << 2))];
        if (grow < NN) *(uint4*)(g_h1h + grow * C1 + 8 * w4) = v;
    }
}

// ---- conv1 aggregation: 2 edges/warp, fp16 inner accumulation (flush every 8 edges) ----
__global__ void k_agg1(const float* __restrict__ b1) {
    int gw = (blockIdx.x * blockDim.x + threadIdx.x) >> 5;
    if (gw >= NN) return;
    int lane = threadIdx.x & 31;
    int half = lane >> 4, l16 = lane & 15;
    int colbase = l16 * 8;
    int head = l16 >> 2;
    float adh = g_ad1[gw * 4 + head];
    int beg = g_rs[gw], end = g_rs[gw + 1];

    float sum = 0.f;
    float acc[8];
    #pragma unroll
    for (int i = 0; i < 8; i++) acc[i] = 0.f;

    int j = beg;
    for (; j + 8 <= end; j += 8) {                     // 8-edge block: fp16 partials
        __half2 ah0 = __float2half2_rn(0.f), ah1 = ah0, ah2 = ah0, ah3 = ah0;
        #pragma unroll
        for (int q = 0; q < 4; q++) {
            int s = g_csr[j + 2 * q + half];
            float a = g_as1[s * 4 + head];
            uint4 u = *(const uint4*)(g_h1h + s * C1 + colbase);
            float e = ex2(lrelu(a + adh));
            sum += e;
            __half2 eh = __float2half2_rn(e);
            ah0 = __hfma2(eh, *(__half2*)&u.x, ah0);
            ah1 = __hfma2(eh, *(__half2*)&u.y, ah1);
            ah2 = __hfma2(eh, *(__half2*)&u.z, ah2);
            ah3 = __hfma2(eh, *(__half2*)&u.w, ah3);
        }
        float2 t0 = __half22float2(ah0), t1 = __half22float2(ah1);
        float2 t2 = __half22float2(ah2), t3 = __half22float2(ah3);
        acc[0] += t0.x; acc[1] += t0.y; acc[2] += t1.x; acc[3] += t1.y;
        acc[4] += t2.x; acc[5] += t2.y; acc[6] += t3.x; acc[7] += t3.y;
    }
    for (; j + 2 <= end; j += 2) {                     // tail pairs: fp32 path
        int s = g_csr[j + half];
        float a = g_as1[s * 4 + head];
        uint4 u = *(const uint4*)(g_h1h + s * C1 + colbase);
        float e = ex2(lrelu(a + adh));
        sum += e;
        float2 f0 = __half22float2(*(__half2*)&u.x);
        float2 f1 = __half22float2(*(__half2*)&u.y);
        float2 f2 = __half22float2(*(__half2*)&u.z);
        float2 f3 = __half22float2(*(__half2*)&u.w);
        acc[0] += e * f0.x; acc[1] += e * f0.y;
        acc[2] += e * f1.x; acc[3] += e * f1.y;
        acc[4] += e * f2.x; acc[5] += e * f2.y;
        acc[6] += e * f3.x; acc[7] += e * f3.y;
    }
    if (j < end && half == 0) {                        // odd tail: A-half only
        int s = g_csr[j];
        float a = g_as1[s * 4 + head];
        uint4 u = *(const uint4*)(g_h1h + s * C1 + colbase);
        float e = ex2(lrelu(a + adh));
        sum += e;
        float2 f0 = __half22float2(*(__half2*)&u.x);
        float2 f1 = __half22float2(*(__half2*)&u.y);
        float2 f2 = __half22float2(*(__half2*)&u.z);
        float2 f3 = __half22float2(*(__half2*)&u.w);
        acc[0] += e * f0.x; acc[1] += e * f0.y;
        acc[2] += e * f1.x; acc[3] += e * f1.y;
        acc[4] += e * f2.x; acc[5] += e * f2.y;
        acc[6] += e * f3.x; acc[7] += e * f3.y;
    }
    // merge the two halves
    sum += __shfl_xor_sync(0xffffffffu, sum, 16);
    #pragma unroll
    for (int i = 0; i < 8; i++) acc[i] += __shfl_xor_sync(0xffffffffu, acc[i], 16);

    if (half == 0) {
        float inv = 1.0f / (sum + 1e-16f);
        float4 bva = *(const float4*)(b1 + colbase);
        float4 bvb = *(const float4*)(b1 + colbase + 4);
        __half2 o0 = __floats2half2_rn(elu1(acc[0] * inv + bva.x), elu1(acc[1] * inv + bva.y));
        __half2 o1 = __floats2half2_rn(elu1(acc[2] * inv + bva.z), elu1(acc[3] * inv + bva.w));
        __half2 o2 = __floats2half2_rn(elu1(acc[4] * inv + bvb.x), elu1(acc[5] * inv + bvb.y));
        __half2 o3 = __floats2half2_rn(elu1(acc[6] * inv + bvb.z), elu1(acc[7] * inv + bvb.w));
        uint4 o = make_uint4(*(unsigned*)&o0, *(unsigned*)&o1, *(unsigned*)&o2, *(unsigned*)&o3);
        *(uint4*)(g_x2h + gw * C1 + colbase) = o;
    }
}

// ---------------- GEMM2 (HMMA): h2 = x2 @ W2, fp16 out + attention scalars ----------------
__global__ void __launch_bounds__(128) k_gemm2(
        const float* __restrict__ att_s, const float* __restrict__ att_d) {
    __shared__ __align__(16) __half xs[MB * 128];    // 16KB; reused as stage
    __shared__ __align__(16) __half ws[C2 * 128];    // 16KB
    __shared__ float s_part[2][MB], d_part[2][MB];
    int tid = threadIdx.x;
    int row0 = blockIdx.x * MB;

    {
        const uint4* wsrc = (const uint4*)g_w2t;
        uint4* wdst = (uint4*)ws;
        #pragma unroll
        for (int i = 0; i < 8; i++) wdst[tid + 128 * i] = wsrc[tid + 128 * i];
    }
    #pragma unroll
    for (int i = 0; i < 8; i++) {
        int idx = tid + 128 * i;
        int m = idx >> 4, cc = idx & 15;
        int gm = row0 + m; if (gm > NN - 1) gm = NN - 1;
        uint4 pk = *(const uint4*)(g_x2h + gm * C1 + cc * 8);
        int sc = cc ^ (m & 7);
        *(uint4*)(xs + m * 128 + sc * 8) = pk;
    }
    __syncthreads();

    int w = tid >> 5, lane = tid & 31;
    int mw = w >> 1, nw = w & 1;
    int i8 = lane >> 3, r8 = lane & 7;
    uint32_t xbase = (uint32_t)__cvta_generic_to_shared(xs);
    uint32_t wbase = (uint32_t)__cvta_generic_to_shared(ws);

    int rowA[2], rowB[2];
    #pragma unroll
    for (int mt = 0; mt < 2; mt++) rowA[mt] = mw * 32 + mt * 16 + (i8 & 1) * 8 + r8;
    #pragma unroll
    for (int p = 0; p < 2; p++)   rowB[p] = nw * 32 + p * 16 + (i8 >> 1) * 8 + r8;
    int kcA_off = (i8 >> 1), kcB_off = (i8 & 1);

    float c[2][4][4];
    #pragma unroll
    for (int mt = 0; mt < 2; mt++)
        #pragma unroll
        for (int nt = 0; nt < 4; nt++)
            #pragma unroll
            for (int q = 0; q < 4; q++) c[mt][nt][q] = 0.f;

    #pragma unroll
    for (int kt = 0; kt < 8; kt++) {
        uint32_t A[2][4], B[2][4];
        #pragma unroll
        for (int mt = 0; mt < 2; mt++) {
            int kc = kt * 2 + kcA_off;
            uint32_t addr = xbase + rowA[mt] * 256 + (((kc ^ (rowA[mt] & 7))) << 4);
            ldsm4(A[mt][0], A[mt][1], A[mt][2], A[mt][3], addr);
        }
        #pragma unroll
        for (int p = 0; p < 2; p++) {
            int kc = kt * 2 + kcB_off;
            uint32_t addr = wbase + rowB[p] * 256 + (((kc ^ (rowB[p] & 7))) << 4);
            ldsm4(B[p][0], B[p][1], B[p][2], B[p][3], addr);
        }
        #pragma unroll
        for (int mt = 0; mt < 2; mt++) {
            mma16816(c[mt][0], A[mt], B[0][0], B[0][1]);
            mma16816(c[mt][1], A[mt], B[0][2], B[0][3]);
            mma16816(c[mt][2], A[mt], B[1][0], B[1][1]);
            mma16816(c[mt][3], A[mt], B[1][2], B[1][3]);
        }
    }
    __syncthreads();                                   // xs reads done; reuse as stage

    uint32_t* stg = (uint32_t*)xs;                     // 64 rows x 32 words
    int quad = lane & 3;
    #pragma unroll
    for (int mt = 0; mt < 2; mt++) {
        int rlo_l = mw * 32 + mt * 16 + (lane >> 2);
        int rhi_l = rlo_l + 8;
        int sw = (rlo_l & 7) << 2;
        float slo = 0.f, shi = 0.f, dlo = 0.f, dhi = 0.f;
        #pragma unroll
        for (int nt = 0; nt < 4; nt++) {
            int cb = nw * 32 + nt * 8 + 2 * quad;
            float as0 = att_s[cb], as1 = att_s[cb + 1];
            float ad0 = att_d[cb], ad1 = att_d[cb + 1];
            float v0 = c[mt][nt][0], v1 = c[mt][nt][1];
            float v2 = c[mt][nt][2], v3 = c[mt][nt][3];
            slo += v0 * as0 + v1 * as1;  dlo += v0 * ad0 + v1 * ad1;
            shi += v2 * as0 + v3 * as1;  dhi += v2 * ad0 + v3 * ad1;
            int wcol = cb >> 1;                        // 0..31
            __half2 hlo = __floats2half2_rn(v0, v1);
            __half2 hhi = __floats2half2_rn(v2, v3);
            stg[rlo_l * 32 + (wcol ^ sw)] = *(uint32_t*)&hlo;
            stg[rhi_l * 32 + (wcol ^ sw)] = *(uint32_t*)&hhi;
        }
        #pragma unroll
        for (int o = 1; o <= 2; o <<= 1) {
            slo += __shfl_xor_sync(0xffffffffu, slo, o);
            shi += __shfl_xor_sync(0xffffffffu, shi, o);
            dlo += __shfl_xor_sync(0xffffffffu, dlo, o);
            dhi += __shfl_xor_sync(0xffffffffu, dhi, o);
        }
        if (quad == 0) {
            s_part[nw][rlo_l] = slo;  d_part[nw][rlo_l] = dlo;
            s_part[nw][rhi_l] = shi;  d_part[nw][rhi_l] = dhi;
        }
    }
    __syncthreads();
    #pragma unroll
    for (int i = 0; i < 4; i++) {
        int q = tid + 128 * i;                         // 512 uint4
        int row = q >> 3, w4 = q & 7;
        int grow = row0 + row;
        uint4 v = *(uint4*)&stg[row * 32 + ((4 * w4) ^ ((row & 7) << 2))];
        if (grow < NN) *(uint4*)(g_h2h + grow * C2 + 8 * w4) = v;
    }
    if (tid < MB) {
        int row = row0 + tid;
        if (row < NN) {
            g_as2[row] = (s_part[0][tid] + s_part[1][tid]) * LOG2E;
            g_ad2[row] = (d_part[0][tid] + d_part[1][tid]) * LOG2E;
        }
    }
}

// ---- conv2 aggregation: 2 edges/warp, fp16 inner accumulation (flush every 8 edges) ----
__global__ void k_agg2(const float* __restrict__ b2) {
    int gw = (blockIdx.x * blockDim.x + threadIdx.x) >> 5;
    if (gw >= NN) return;
    int lane = threadIdx.x & 31;
    int half = lane >> 4, l16 = lane & 15;
    int colbase = l16 * 4;
    float ad = g_ad2[gw];
    int beg = g_rs[gw], end = g_rs[gw + 1];

    float sum = 0.f;
    float acc[4];
    #pragma unroll
    for (int i = 0; i < 4; i++) acc[i] = 0.f;

    int j = beg;
    for (; j + 8 <= end; j += 8) {                     // 8-edge block: fp16 partials
        __half2 ah0 = __float2half2_rn(0.f), ah1 = ah0;
        #pragma unroll
        for (int q = 0; q < 4; q++) {
            int s = g_csr[j + 2 * q + half];
            float a = g_as2[s];
            uint2 u = *(const uint2*)(g_h2h + s * C2 + colbase);
            float e = ex2(lrelu(a + ad));
            sum += e;
            __half2 eh = __float2half2_rn(e);
            ah0 = __hfma2(eh, *(__half2*)&u.x, ah0);
            ah1 = __hfma2(eh, *(__half2*)&u.y, ah1);
        }
        float2 t0 = __half22float2(ah0), t1 = __half22float2(ah1);
        acc[0] += t0.x; acc[1] += t0.y; acc[2] += t1.x; acc[3] += t1.y;
    }
    for (; j + 2 <= end; j += 2) {                     // tail pairs: fp32 path
        int s = g_csr[j + half];
        float a = g_as2[s];
        uint2 u = *(const uint2*)(g_h2h + s * C2 + colbase);
        float e = ex2(lrelu(a + ad));
        sum += e;
        float2 f0 = __half22float2(*(__half2*)&u.x);
        float2 f1 = __half22float2(*(__half2*)&u.y);
        acc[0] += e * f0.x; acc[1] += e * f0.y;
        acc[2] += e * f1.x; acc[3] += e * f1.y;
    }
    if (j < end && half == 0) {
        int s = g_csr[j];
        float a = g_as2[s];
        uint2 u = *(const uint2*)(g_h2h + s * C2 + colbase);
        float e = ex2(lrelu(a + ad));
        sum += e;
        float2 f0 = __half22float2(*(__half2*)&u.x);
        float2 f1 = __half22float2(*(__half2*)&u.y);
        acc[0] += e * f0.x; acc[1] += e * f0.y;
        acc[2] += e * f1.x; acc[3] += e * f1.y;
    }
    sum += __shfl_xor_sync(0xffffffffu, sum, 16);
    #pragma unroll
    for (int i = 0; i < 4; i++) acc[i] += __shfl_xor_sync(0xffffffffu, acc[i], 16);

    if (half == 0) {
        float inv = 1.0f / (sum + 1e-16f);
        float4 bv = *(const float4*)(b2 + colbase);
        __half2 o0 = __floats2half2_rn(elu1(acc[0] * inv + bv.x), elu1(acc[1] * inv + bv.y));
        __half2 o1 = __floats2half2_rn(elu1(acc[2] * inv + bv.z), elu1(acc[3] * inv + bv.w));
        uint2 o = make_uint2(*(unsigned*)&o0, *(unsigned*)&o1);
        *(uint2*)(g_out2h + gw * C2 + colbase) = o;
    }
}

// ---------------- fused global mean pool + classifier (1 block per graph) ----------------
__global__ void __launch_bounds__(256) k_poolfinal(
        const int* __restrict__ batch, const float* __restrict__ Wc,
        const float* __restrict__ bc, float* __restrict__ out) {
    __shared__ int sb[2];
    __shared__ float red[4][C2];
    __shared__ float pooled[C2];
    int g = blockIdx.x, tid = threadIdx.x;
    if (tid < 2) {
        int target = g + tid;
        int lo = 0, hi = NN;
        while (lo < hi) { int mid = (lo + hi) >> 1; if (batch[mid] < target) lo = mid + 1; else hi = mid; }
        sb[tid] = lo;
    }
    __syncthreads();
    int lo = sb[0], hi = sb[1];
    int ch = tid & 63, grp = tid >> 6;
    float a0 = 0.f, a1 = 0.f;
    int n = lo + grp;
    for (; n + 4 < hi; n += 8) {
        a0 += __half2float(g_out2h[n * C2 + ch]);
        a1 += __half2float(g_out2h[(n + 4) * C2 + ch]);
    }
    if (n < hi) a0 += __half2float(g_out2h[n * C2 + ch]);
    red[grp][ch] = a0 + a1;
    __syncthreads();
    if (tid < C2) {
        float cnt = (float)(hi - lo); if (cnt < 1.f) cnt = 1.f;
        pooled[tid] = (red[0][tid] + red[1][tid] + red[2][tid] + red[3][tid]) / cnt;
    }
    __syncthreads();
    if (tid < NCLS) {
        float s = 0.f;
        #pragma unroll
        for (int c2 = 0; c2 < C2; c2++) s += pooled[c2] * Wc[c2 * NCLS + tid];
        out[g * NCLS + tid] = s + bc[tid];
    }
}

// ---------------- launch: CSR chain || (prepW + gemm1), join before agg1 ----------------
extern "C" void kernel_launch(void* const* d_in, const int* in_sizes, int n_in,
                              void* d_out, int out_size) {
    const float* x     = (const float*)d_in[0];
    const int*   ei    = (const int*)  d_in[1];   // [2, E] row-major
    const int*   batch = (const int*)  d_in[2];
    const float* W1    = (const float*)d_in[3];
    const float* atts1 = (const float*)d_in[4];
    const float* attd1 = (const float*)d_in[5];
    const float* b1    = (const float*)d_in[6];
    const float* W2    = (const float*)d_in[7];
    const float* atts2 = (const float*)d_in[8];
    const float* attd2 = (const float*)d_in[9];
    const float* b2    = (const float*)d_in[10];
    const float* Wc    = (const float*)d_in[11];
    const float* bc    = (const float*)d_in[12];
    float* out = (float*)d_out;

    int gemm_grid = (NN + MB - 1) / MB;   // 1563

    // fresh stream/events per call (never destroyed: kernel_launch runs only a
    // handful of times; destroy-during-capture is illegal). Same work every call.
    cudaStream_t s1;
    cudaEvent_t evF, evJ;
    cudaStreamCreateWithFlags(&s1, cudaStreamNonBlocking);
    cudaEventCreateWithFlags(&evF, cudaEventDisableTiming);
    cudaEventCreateWithFlags(&evJ, cudaEventDisableTiming);

    cudaEventRecord(evF, 0);                   // fork from legacy stream
    cudaStreamWaitEvent(s1, evF, 0);

    // legacy stream: CSR build chain (latency/L2-bound)
    k_hist     <<<(EE / 4 + 255) / 256, 256>>>(ei + EE);
    k_scanA    <<<NCHUNK, 256>>>();
    k_scanC    <<<(NN + 511) / 512, 512>>>();
    k_scatter  <<<(SCAT_E4 + NN + 255) / 256, 256>>>(ei);

    // side stream: weight prep + GEMM1 (tensor-bound), fully independent
    k_prepW    <<<(3072 + 255) / 256, 256, 0, s1>>>(W1, W2);
    k_gemm1    <<<gemm_grid, 256, 0, s1>>>(x, atts1, attd1);

    cudaEventRecord(evJ, s1);                  // join
    cudaStreamWaitEvent(0, evJ, 0);

    k_agg1     <<<(NN * 32 + 255) / 256, 256>>>(b1);
    k_gemm2    <<<gemm_grid, 128>>>(atts2, attd2);
    k_agg2     <<<(NN * 32 + 255) / 256, 256>>>(b2);
    k_poolfinal<<<NGRAPH, 256>>>(batch, Wc, bc, out);
}

// round 16
// speedup vs baseline: 1.0511x; 1.0166x over previous
#include <cuda_runtime.h>
#include <cuda_fp16.h>
#include <math.h>
#include <stdint.h>

#define NN      100000
#define EE      1600000
#define NETOT   (EE + NN)           // edges + self loops
#define INC     128
#define C1      128                 // heads(4) * hid(32)
#define C2      64
#define HEADS   4
#define NGRAPH  64
#define NCLS    2
#define NCHUNK  ((NN + 255) / 256)  // 391
#define MB      64                  // gemm rows per block
#define SCAT_E4 (EE / 4)            // 400000 (exact)
#define LOG2E   1.44269504f

// ---------------- scratch (static __device__, no allocations) ----------------
__device__ int    g_deg[NN];        // zero at entry (BSS-zero; re-zeroed by scanC each call)
__device__ int    g_rs[NN + 1];
__device__ int    g_epos[EE];       // per-edge slot within its dst segment
__device__ int    g_csr[NETOT];
__device__ int    g_csum[512];
__device__ __align__(16) __half g_h1h[NN * C1];
__device__ float  g_as1[NN * HEADS];   // pre-scaled by log2(e)
__device__ float  g_ad1[NN * HEADS];   // pre-scaled by log2(e)
__device__ __align__(16) __half g_x2h[NN * C1];
__device__ __align__(16) __half g_h2h[NN * C2];
__device__ float  g_as2[NN];           // pre-scaled by log2(e)
__device__ float  g_ad2[NN];           // pre-scaled by log2(e)
__device__ __align__(16) __half g_out2h[NN * C2];
__device__ __align__(16) __half g_w1t[C1 * INC];   // W1^T fp16, ldsm-swizzled
__device__ __align__(16) __half g_w2t[C2 * C1];    // W2^T fp16, ldsm-swizzled

__device__ __forceinline__ float lrelu(float x) { return x > 0.f ? x : 0.2f * x; }
__device__ __forceinline__ float elu1(float x)  { return x > 0.f ? x : expm1f(x); }
__device__ __forceinline__ float ex2(float x) {
    float r;
    asm("ex2.approx.ftz.f32 %0, %1;" : "=f"(r) : "f"(x));
    return r;
}

__device__ __forceinline__ void ldsm4(uint32_t& r0, uint32_t& r1, uint32_t& r2, uint32_t& r3,
                                      uint32_t addr) {
    asm volatile("ldmatrix.sync.aligned.m8n8.x4.shared.b16 {%0,%1,%2,%3}, [%4];"
                 : "=r"(r0), "=r"(r1), "=r"(r2), "=r"(r3) : "r"(addr));
}
__device__ __forceinline__ void mma16816(float* c, const uint32_t* a, uint32_t b0, uint32_t b1) {
    asm volatile("mma.sync.aligned.m16n8k16.row.col.f32.f16.f16.f32 "
                 "{%0,%1,%2,%3},{%4,%5,%6,%7},{%8,%9},{%0,%1,%2,%3};"
                 : "+f"(c[0]), "+f"(c[1]), "+f"(c[2]), "+f"(c[3])
                 : "r"(a[0]), "r"(a[1]), "r"(a[2]), "r"(a[3]), "r"(b0), "r"(b1));
}

// ---------------- CSR build ----------------
__global__ void k_hist(const int* __restrict__ dst) {
    int e4 = blockIdx.x * blockDim.x + threadIdx.x;
    int e = e4 * 4;
    if (e + 3 < EE) {
        int4 d = *(const int4*)(dst + e);
        int4 p;
        p.x = atomicAdd(&g_deg[d.x], 1);
        p.y = atomicAdd(&g_deg[d.y], 1);
        p.z = atomicAdd(&g_deg[d.z], 1);
        p.w = atomicAdd(&g_deg[d.w], 1);
        *(int4*)(g_epos + e) = p;
    } else {
        for (; e < EE; e++) g_epos[e] = atomicAdd(&g_deg[dst[e]], 1);
    }
}

__global__ void k_scanA() {
    __shared__ int sh[256];
    int i = blockIdx.x * 256 + threadIdx.x;
    int v = (i < NN) ? (g_deg[i] + 1) : 0;    // +1 = self loop
    sh[threadIdx.x] = v;
    __syncthreads();
    #pragma unroll
    for (int off = 1; off < 256; off <<= 1) {
        int t = (threadIdx.x >= off) ? sh[threadIdx.x - off] : 0;
        __syncthreads();
        sh[threadIdx.x] += t;
        __syncthreads();
    }
    if (i < NN) g_rs[i] = sh[threadIdx.x] - v;     // chunk-local exclusive
    if (threadIdx.x == 255) g_csum[blockIdx.x] = sh[255];
}

__global__ void __launch_bounds__(512) k_scanC() {
    __shared__ int sh[512];
    int t = threadIdx.x;
    int v = (t < NCHUNK) ? g_csum[t] : 0;
    sh[t] = v;
    __syncthreads();
    #pragma unroll
    for (int off = 1; off < 512; off <<= 1) {
        int tv = (t >= off) ? sh[t - off] : 0;
        __syncthreads();
        sh[t] += tv;
        __syncthreads();
    }
    sh[t] -= v;                                    // exclusive
    __syncthreads();
    int i = blockIdx.x * 512 + t;
    if (i < NN) {
        g_rs[i] += sh[i >> 8];
        g_deg[i] = 0;                              // reset for next invocation
    }
    if (i == 0) g_rs[NN] = NETOT;
}

__global__ void k_scatter(const int* __restrict__ ei) {
    int idx = blockIdx.x * blockDim.x + threadIdx.x;
    if (idx < SCAT_E4) {
        int e = idx * 4;
        int4 s = *(const int4*)(ei + e);
        int4 d = *(const int4*)(ei + EE + e);
        int4 p = *(const int4*)(g_epos + e);
        g_csr[g_rs[d.x] + p.x] = s.x;
        g_csr[g_rs[d.y] + p.y] = s.y;
        g_csr[g_rs[d.z] + p.z] = s.z;
        g_csr[g_rs[d.w] + p.w] = s.w;
    } else {
        int n = idx - SCAT_E4;
        if (n < NN) g_csr[g_rs[n + 1] - 1] = n;    // self loop
    }
}

// one-time weight transpose + fp16 + ldsm swizzle bake
__global__ void k_prepW(const float* __restrict__ W1, const float* __restrict__ W2) {
    int idx = blockIdx.x * blockDim.x + threadIdx.x;
    if (idx < 128 * 16) {
        int n = idx >> 4, kc = idx & 15;
        int sc = kc ^ (n & 7);
        #pragma unroll
        for (int j = 0; j < 8; j++)
            g_w1t[n * 128 + (sc << 3) + j] = __float2half(W1[(kc * 8 + j) * C1 + n]);
    } else if (idx < 128 * 16 + 64 * 16) {
        int q = idx - 128 * 16;
        int n = q >> 4, kc = q & 15;
        int sc = kc ^ (n & 7);
        #pragma unroll
        for (int j = 0; j < 8; j++)
            g_w2t[n * 128 + (sc << 3) + j] = __float2half(W2[(kc * 8 + j) * C2 + n]);
    }
}

// ---------------- GEMM1 (HMMA): h1 = x @ W1, fp16 out + attention scalars ----------------
__global__ void __launch_bounds__(256) k_gemm1(
        const float* __restrict__ x,
        const float* __restrict__ att_s, const float* __restrict__ att_d) {
    __shared__ __align__(16) __half xs[MB * 128];     // 16KB; reused as stage buffer
    __shared__ __align__(16) __half ws[128 * 128];    // 32KB
    int tid = threadIdx.x;
    int row0 = blockIdx.x * MB;

    {
        const uint4* wsrc = (const uint4*)g_w1t;
        uint4* wdst = (uint4*)ws;
        #pragma unroll
        for (int i = 0; i < 8; i++) wdst[tid + 256 * i] = wsrc[tid + 256 * i];
    }
    #pragma unroll
    for (int i = 0; i < 4; i++) {
        int idx = tid + 256 * i;
        int m = idx >> 4, cc = idx & 15;
        int gm = row0 + m; if (gm > NN - 1) gm = NN - 1;
        const float4* xp = (const float4*)(x + gm * INC + cc * 8);
        float4 v0 = xp[0], v1 = xp[1];
        __half2 h0 = __floats2half2_rn(v0.x, v0.y);
        __half2 h1 = __floats2half2_rn(v0.z, v0.w);
        __half2 h2 = __floats2half2_rn(v1.x, v1.y);
        __half2 h3 = __floats2half2_rn(v1.z, v1.w);
        uint4 pk = make_uint4(*(unsigned*)&h0, *(unsigned*)&h1, *(unsigned*)&h2, *(unsigned*)&h3);
        int sc = cc ^ (m & 7);
        *(uint4*)(xs + m * 128 + sc * 8) = pk;
    }
    __syncthreads();

    int w = tid >> 5, lane = tid & 31;
    int mw = w >> 2, nw = w & 3;
    int i8 = lane >> 3, r8 = lane & 7;
    uint32_t xbase = (uint32_t)__cvta_generic_to_shared(xs);
    uint32_t wbase = (uint32_t)__cvta_generic_to_shared(ws);

    int rowA[2], rowB[2];
    #pragma unroll
    for (int mt = 0; mt < 2; mt++) rowA[mt] = mw * 32 + mt * 16 + (i8 & 1) * 8 + r8;
    #pragma unroll
    for (int p = 0; p < 2; p++)   rowB[p] = nw * 32 + p * 16 + (i8 >> 1) * 8 + r8;
    int kcA_off = (i8 >> 1);
    int kcB_off = (i8 & 1);

    float c[2][4][4];
    #pragma unroll
    for (int mt = 0; mt < 2; mt++)
        #pragma unroll
        for (int nt = 0; nt < 4; nt++)
            #pragma unroll
            for (int q = 0; q < 4; q++) c[mt][nt][q] = 0.f;

    #pragma unroll
    for (int kt = 0; kt < 8; kt++) {
        uint32_t A[2][4], B[2][4];
        #pragma unroll
        for (int mt = 0; mt < 2; mt++) {
            int kc = kt * 2 + kcA_off;
            uint32_t addr = xbase + rowA[mt] * 256 + (((kc ^ (rowA[mt] & 7))) << 4);
            ldsm4(A[mt][0], A[mt][1], A[mt][2], A[mt][3], addr);
        }
        #pragma unroll
        for (int p = 0; p < 2; p++) {
            int kc = kt * 2 + kcB_off;
            uint32_t addr = wbase + rowB[p] * 256 + (((kc ^ (rowB[p] & 7))) << 4);
            ldsm4(B[p][0], B[p][1], B[p][2], B[p][3], addr);
        }
        #pragma unroll
        for (int mt = 0; mt < 2; mt++) {
            mma16816(c[mt][0], A[mt], B[0][0], B[0][1]);
            mma16816(c[mt][1], A[mt], B[0][2], B[0][3]);
            mma16816(c[mt][2], A[mt], B[1][0], B[1][1]);
            mma16816(c[mt][3], A[mt], B[1][2], B[1][3]);
        }
    }
    __syncthreads();                                   // xs reads done; reuse as stage

    uint32_t* stg = (uint32_t*)xs;                     // 64 rows x 64 words
    int quad = lane & 3;
    #pragma unroll
    for (int mt = 0; mt < 2; mt++) {
        int rlo_l = mw * 32 + mt * 16 + (lane >> 2);
        int rhi_l = rlo_l + 8;
        int rlo = row0 + rlo_l, rhi = row0 + rhi_l;
        int sw = (rlo_l & 7) << 2;                     // same for rhi_l
        float slo = 0.f, shi = 0.f, dlo = 0.f, dhi = 0.f;
        #pragma unroll
        for (int nt = 0; nt < 4; nt++) {
            int cb = nw * 32 + nt * 8 + 2 * quad;
            float as0 = att_s[cb], as1 = att_s[cb + 1];
            float ad0 = att_d[cb], ad1 = att_d[cb + 1];
            float v0 = c[mt][nt][0], v1 = c[mt][nt][1];
            float v2 = c[mt][nt][2], v3 = c[mt][nt][3];
            slo += v0 * as0 + v1 * as1;  dlo += v0 * ad0 + v1 * ad1;
            shi += v2 * as0 + v3 * as1;  dhi += v2 * ad0 + v3 * ad1;
            int wcol = cb >> 1;
            __half2 hlo = __floats2half2_rn(v0, v1);
            __half2 hhi = __floats2half2_rn(v2, v3);
            stg[rlo_l * 64 + (wcol ^ sw)] = *(uint32_t*)&hlo;
            stg[rhi_l * 64 + (wcol ^ sw)] = *(uint32_t*)&hhi;
        }
        #pragma unroll
        for (int o = 1; o <= 2; o <<= 1) {
            slo += __shfl_xor_sync(0xffffffffu, slo, o);
            shi += __shfl_xor_sync(0xffffffffu, shi, o);
            dlo += __shfl_xor_sync(0xffffffffu, dlo, o);
            dhi += __shfl_xor_sync(0xffffffffu, dhi, o);
        }
        if (quad == 0) {
            if (rlo < NN) { g_as1[rlo * 4 + nw] = slo * LOG2E; g_ad1[rlo * 4 + nw] = dlo * LOG2E; }
            if (rhi < NN) { g_as1[rhi * 4 + nw] = shi * LOG2E; g_ad1[rhi * 4 + nw] = dhi * LOG2E; }
        }
    }
    __syncthreads();
    #pragma unroll
    for (int i = 0; i < 4; i++) {
        int q = tid + 256 * i;                         // 1024 uint4
        int row = q >> 4, w4 = q & 15;
        int grow = row0 + row;
        uint4 v = *(uint4*)&stg[row * 64 + ((4 * w4) ^ ((row & 7) << 2))];
        if (grow < NN) *(uint4*)(g_h1h + grow * C1 + 8 * w4) = v;
    }
}

// ---- conv1 aggregation: 2 edges/warp, fp16 inner accumulation, high occupancy ----
__global__ void __launch_bounds__(256, 6) k_agg1(const float* __restrict__ b1) {
    int gw = (blockIdx.x * blockDim.x + threadIdx.x) >> 5;
    if (gw >= NN) return;
    int lane = threadIdx.x & 31;
    int half = lane >> 4, l16 = lane & 15;
    int colbase = l16 * 8;
    int head = l16 >> 2;
    float adh = __ldg(&g_ad1[gw * 4 + head]);
    int beg = __ldg(&g_rs[gw]), end = __ldg(&g_rs[gw + 1]);

    float sum = 0.f;
    float acc[8];
    #pragma unroll
    for (int i = 0; i < 8; i++) acc[i] = 0.f;

    int j = beg;
    for (; j + 8 <= end; j += 8) {                     // 8-edge block: fp16 partials
        __half2 ah0 = __float2half2_rn(0.f), ah1 = ah0, ah2 = ah0, ah3 = ah0;
        #pragma unroll
        for (int q = 0; q < 4; q++) {
            int s = __ldg(&g_csr[j + 2 * q + half]);
            float a = __ldg(&g_as1[s * 4 + head]);
            uint4 u = __ldg((const uint4*)(g_h1h + s * C1 + colbase));
            float e = ex2(lrelu(a + adh));
            sum += e;
            __half2 eh = __float2half2_rn(e);
            ah0 = __hfma2(eh, *(__half2*)&u.x, ah0);
            ah1 = __hfma2(eh, *(__half2*)&u.y, ah1);
            ah2 = __hfma2(eh, *(__half2*)&u.z, ah2);
            ah3 = __hfma2(eh, *(__half2*)&u.w, ah3);
        }
        float2 t0 = __half22float2(ah0), t1 = __half22float2(ah1);
        float2 t2 = __half22float2(ah2), t3 = __half22float2(ah3);
        acc[0] += t0.x; acc[1] += t0.y; acc[2] += t1.x; acc[3] += t1.y;
        acc[4] += t2.x; acc[5] += t2.y; acc[6] += t3.x; acc[7] += t3.y;
    }
    for (; j + 2 <= end; j += 2) {                     // tail pairs: fp32 path
        int s = __ldg(&g_csr[j + half]);
        float a = __ldg(&g_as1[s * 4 + head]);
        uint4 u = __ldg((const uint4*)(g_h1h + s * C1 + colbase));
        float e = ex2(lrelu(a + adh));
        sum += e;
        float2 f0 = __half22float2(*(__half2*)&u.x);
        float2 f1 = __half22float2(*(__half2*)&u.y);
        float2 f2 = __half22float2(*(__half2*)&u.z);
        float2 f3 = __half22float2(*(__half2*)&u.w);
        acc[0] += e * f0.x; acc[1] += e * f0.y;
        acc[2] += e * f1.x; acc[3] += e * f1.y;
        acc[4] += e * f2.x; acc[5] += e * f2.y;
        acc[6] += e * f3.x; acc[7] += e * f3.y;
    }
    if (j < end && half == 0) {                        // odd tail: A-half only
        int s = __ldg(&g_csr[j]);
        float a = __ldg(&g_as1[s * 4 + head]);
        uint4 u = __ldg((const uint4*)(g_h1h + s * C1 + colbase));
        float e = ex2(lrelu(a + adh));
        sum += e;
        float2 f0 = __half22float2(*(__half2*)&u.x);
        float2 f1 = __half22float2(*(__half2*)&u.y);
        float2 f2 = __half22float2(*(__half2*)&u.z);
        float2 f3 = __half22float2(*(__half2*)&u.w);
        acc[0] += e * f0.x; acc[1] += e * f0.y;
        acc[2] += e * f1.x; acc[3] += e * f1.y;
        acc[4] += e * f2.x; acc[5] += e * f2.y;
        acc[6] += e * f3.x; acc[7] += e * f3.y;
    }
    // merge the two halves
    sum += __shfl_xor_sync(0xffffffffu, sum, 16);
    #pragma unroll
    for (int i = 0; i < 8; i++) acc[i] += __shfl_xor_sync(0xffffffffu, acc[i], 16);

    if (half == 0) {
        float inv = 1.0f / (sum + 1e-16f);
        float4 bva = *(const float4*)(b1 + colbase);
        float4 bvb = *(const float4*)(b1 + colbase + 4);
        __half2 o0 = __floats2half2_rn(elu1(acc[0] * inv + bva.x), elu1(acc[1] * inv + bva.y));
        __half2 o1 = __floats2half2_rn(elu1(acc[2] * inv + bva.z), elu1(acc[3] * inv + bva.w));
        __half2 o2 = __floats2half2_rn(elu1(acc[4] * inv + bvb.x), elu1(acc[5] * inv + bvb.y));
        __half2 o3 = __floats2half2_rn(elu1(acc[6] * inv + bvb.z), elu1(acc[7] * inv + bvb.w));
        uint4 o = make_uint4(*(unsigned*)&o0, *(unsigned*)&o1, *(unsigned*)&o2, *(unsigned*)&o3);
        *(uint4*)(g_x2h + gw * C1 + colbase) = o;
    }
}

// ---------------- GEMM2 (HMMA): h2 = x2 @ W2, fp16 out + attention scalars ----------------
__global__ void __launch_bounds__(128) k_gemm2(
        const float* __restrict__ att_s, const float* __restrict__ att_d) {
    __shared__ __align__(16) __half xs[MB * 128];    // 16KB; reused as stage
    __shared__ __align__(16) __half ws[C2 * 128];    // 16KB
    __shared__ float s_part[2][MB], d_part[2][MB];
    int tid = threadIdx.x;
    int row0 = blockIdx.x * MB;

    {
        const uint4* wsrc = (const uint4*)g_w2t;
        uint4* wdst = (uint4*)ws;
        #pragma unroll
        for (int i = 0; i < 8; i++) wdst[tid + 128 * i] = wsrc[tid + 128 * i];
    }
    #pragma unroll
    for (int i = 0; i < 8; i++) {
        int idx = tid + 128 * i;
        int m = idx >> 4, cc = idx & 15;
        int gm = row0 + m; if (gm > NN - 1) gm = NN - 1;
        uint4 pk = *(const uint4*)(g_x2h + gm * C1 + cc * 8);
        int sc = cc ^ (m & 7);
        *(uint4*)(xs + m * 128 + sc * 8) = pk;
    }
    __syncthreads();

    int w = tid >> 5, lane = tid & 31;
    int mw = w >> 1, nw = w & 1;
    int i8 = lane >> 3, r8 = lane & 7;
    uint32_t xbase = (uint32_t)__cvta_generic_to_shared(xs);
    uint32_t wbase = (uint32_t)__cvta_generic_to_shared(ws);

    int rowA[2], rowB[2];
    #pragma unroll
    for (int mt = 0; mt < 2; mt++) rowA[mt] = mw * 32 + mt * 16 + (i8 & 1) * 8 + r8;
    #pragma unroll
    for (int p = 0; p < 2; p++)   rowB[p] = nw * 32 + p * 16 + (i8 >> 1) * 8 + r8;
    int kcA_off = (i8 >> 1), kcB_off = (i8 & 1);

    float c[2][4][4];
    #pragma unroll
    for (int mt = 0; mt < 2; mt++)
        #pragma unroll
        for (int nt = 0; nt < 4; nt++)
            #pragma unroll
            for (int q = 0; q < 4; q++) c[mt][nt][q] = 0.f;

    #pragma unroll
    for (int kt = 0; kt < 8; kt++) {
        uint32_t A[2][4], B[2][4];
        #pragma unroll
        for (int mt = 0; mt < 2; mt++) {
            int kc = kt * 2 + kcA_off;
            uint32_t addr = xbase + rowA[mt] * 256 + (((kc ^ (rowA[mt] & 7))) << 4);
            ldsm4(A[mt][0], A[mt][1], A[mt][2], A[mt][3], addr);
        }
        #pragma unroll
        for (int p = 0; p < 2; p++) {
            int kc = kt * 2 + kcB_off;
            uint32_t addr = wbase + rowB[p] * 256 + (((kc ^ (rowB[p] & 7))) << 4);
            ldsm4(B[p][0], B[p][1], B[p][2], B[p][3], addr);
        }
        #pragma unroll
        for (int mt = 0; mt < 2; mt++) {
            mma16816(c[mt][0], A[mt], B[0][0], B[0][1]);
            mma16816(c[mt][1], A[mt], B[0][2], B[0][3]);
            mma16816(c[mt][2], A[mt], B[1][0], B[1][1]);
            mma16816(c[mt][3], A[mt], B[1][2], B[1][3]);
        }
    }
    __syncthreads();                                   // xs reads done; reuse as stage

    uint32_t* stg = (uint32_t*)xs;                     // 64 rows x 32 words
    int quad = lane & 3;
    #pragma unroll
    for (int mt = 0; mt < 2; mt++) {
        int rlo_l = mw * 32 + mt * 16 + (lane >> 2);
        int rhi_l = rlo_l + 8;
        int sw = (rlo_l & 7) << 2;
        float slo = 0.f, shi = 0.f, dlo = 0.f, dhi = 0.f;
        #pragma unroll
        for (int nt = 0; nt < 4; nt++) {
            int cb = nw * 32 + nt * 8 + 2 * quad;
            float as0 = att_s[cb], as1 = att_s[cb + 1];
            float ad0 = att_d[cb], ad1 = att_d[cb + 1];
            float v0 = c[mt][nt][0], v1 = c[mt][nt][1];
            float v2 = c[mt][nt][2], v3 = c[mt][nt][3];
            slo += v0 * as0 + v1 * as1;  dlo += v0 * ad0 + v1 * ad1;
            shi += v2 * as0 + v3 * as1;  dhi += v2 * ad0 + v3 * ad1;
            int wcol = cb >> 1;                        // 0..31
            __half2 hlo = __floats2half2_rn(v0, v1);
            __half2 hhi = __floats2half2_rn(v2, v3);
            stg[rlo_l * 32 + (wcol ^ sw)] = *(uint32_t*)&hlo;
            stg[rhi_l * 32 + (wcol ^ sw)] = *(uint32_t*)&hhi;
        }
        #pragma unroll
        for (int o = 1; o <= 2; o <<= 1) {
            slo += __shfl_xor_sync(0xffffffffu, slo, o);
            shi += __shfl_xor_sync(0xffffffffu, shi, o);
            dlo += __shfl_xor_sync(0xffffffffu, dlo, o);
            dhi += __shfl_xor_sync(0xffffffffu, dhi, o);
        }
        if (quad == 0) {
            s_part[nw][rlo_l] = slo;  d_part[nw][rlo_l] = dlo;
            s_part[nw][rhi_l] = shi;  d_part[nw][rhi_l] = dhi;
        }
    }
    __syncthreads();
    #pragma unroll
    for (int i = 0; i < 4; i++) {
        int q = tid + 128 * i;                         // 512 uint4
        int row = q >> 3, w4 = q & 7;
        int grow = row0 + row;
        uint4 v = *(uint4*)&stg[row * 32 + ((4 * w4) ^ ((row & 7) << 2))];
        if (grow < NN) *(uint4*)(g_h2h + grow * C2 + 8 * w4) = v;
    }
    if (tid < MB) {
        int row = row0 + tid;
        if (row < NN) {
            g_as2[row] = (s_part[0][tid] + s_part[1][tid]) * LOG2E;
            g_ad2[row] = (d_part[0][tid] + d_part[1][tid]) * LOG2E;
        }
    }
}

// ---- conv2 aggregation: 2 edges/warp, fp16 inner accumulation, high occupancy ----
__global__ void __launch_bounds__(256, 6) k_agg2(const float* __restrict__ b2) {
    int gw = (blockIdx.x * blockDim.x + threadIdx.x) >> 5;
    if (gw >= NN) return;
    int lane = threadIdx.x & 31;
    int half = lane >> 4, l16 = lane & 15;
    int colbase = l16 * 4;
    float ad = __ldg(&g_ad2[gw]);
    int beg = __ldg(&g_rs[gw]), end = __ldg(&g_rs[gw + 1]);

    float sum = 0.f;
    float acc[4];
    #pragma unroll
    for (int i = 0; i < 4; i++) acc[i] = 0.f;

    int j = beg;
    for (; j + 8 <= end; j += 8) {                     // 8-edge block: fp16 partials
        __half2 ah0 = __float2half2_rn(0.f), ah1 = ah0;
        #pragma unroll
        for (int q = 0; q < 4; q++) {
            int s = __ldg(&g_csr[j + 2 * q + half]);
            float a = __ldg(&g_as2[s]);
            uint2 u = __ldg((const uint2*)(g_h2h + s * C2 + colbase));
            float e = ex2(lrelu(a + ad));
            sum += e;
            __half2 eh = __float2half2_rn(e);
            ah0 = __hfma2(eh, *(__half2*)&u.x, ah0);
            ah1 = __hfma2(eh, *(__half2*)&u.y, ah1);
        }
        float2 t0 = __half22float2(ah0), t1 = __half22float2(ah1);
        acc[0] += t0.x; acc[1] += t0.y; acc[2] += t1.x; acc[3] += t1.y;
    }
    for (; j + 2 <= end; j += 2) {                     // tail pairs: fp32 path
        int s = __ldg(&g_csr[j + half]);
        float a = __ldg(&g_as2[s]);
        uint2 u = __ldg((const uint2*)(g_h2h + s * C2 + colbase));
        float e = ex2(lrelu(a + ad));
        sum += e;
        float2 f0 = __half22float2(*(__half2*)&u.x);
        float2 f1 = __half22float2(*(__half2*)&u.y);
        acc[0] += e * f0.x; acc[1] += e * f0.y;
        acc[2] += e * f1.x; acc[3] += e * f1.y;
    }
    if (j < end && half == 0) {
        int s = __ldg(&g_csr[j]);
        float a = __ldg(&g_as2[s]);
        uint2 u = __ldg((const uint2*)(g_h2h + s * C2 + colbase));
        float e = ex2(lrelu(a + ad));
        sum += e;
        float2 f0 = __half22float2(*(__half2*)&u.x);
        float2 f1 = __half22float2(*(__half2*)&u.y);
        acc[0] += e * f0.x; acc[1] += e * f0.y;
        acc[2] += e * f1.x; acc[3] += e * f1.y;
    }
    sum += __shfl_xor_sync(0xffffffffu, sum, 16);
    #pragma unroll
    for (int i = 0; i < 4; i++) acc[i] += __shfl_xor_sync(0xffffffffu, acc[i], 16);

    if (half == 0) {
        float inv = 1.0f / (sum + 1e-16f);
        float4 bv = *(const float4*)(b2 + colbase);
        __half2 o0 = __floats2half2_rn(elu1(acc[0] * inv + bv.x), elu1(acc[1] * inv + bv.y));
        __half2 o1 = __floats2half2_rn(elu1(acc[2] * inv + bv.z), elu1(acc[3] * inv + bv.w));
        uint2 o = make_uint2(*(unsigned*)&o0, *(unsigned*)&o1);
        *(uint2*)(g_out2h + gw * C2 + colbase) = o;
    }
}

// ---------------- fused global mean pool + classifier (1 block per graph) ----------------
__global__ void __launch_bounds__(256) k_poolfinal(
        const int* __restrict__ batch, const float* __restrict__ Wc,
        const float* __restrict__ bc, float* __restrict__ out) {
    __shared__ int sb[2];
    __shared__ float red[4][C2];
    __shared__ float pooled[C2];
    int g = blockIdx.x, tid = threadIdx.x;
    if (tid < 2) {
        int target = g + tid;
        int lo = 0, hi = NN;
        while (lo < hi) { int mid = (lo + hi) >> 1; if (batch[mid] < target) lo = mid + 1; else hi = mid; }
        sb[tid] = lo;
    }
    __syncthreads();
    int lo = sb[0], hi = sb[1];
    int ch = tid & 63, grp = tid >> 6;
    float a0 = 0.f, a1 = 0.f;
    int n = lo + grp;
    for (; n + 4 < hi; n += 8) {
        a0 += __half2float(g_out2h[n * C2 + ch]);
        a1 += __half2float(g_out2h[(n + 4) * C2 + ch]);
    }
    if (n < hi) a0 += __half2float(g_out2h[n * C2 + ch]);
    red[grp][ch] = a0 + a1;
    __syncthreads();
    if (tid < C2) {
        float cnt = (float)(hi - lo); if (cnt < 1.f) cnt = 1.f;
        pooled[tid] = (red[0][tid] + red[1][tid] + red[2][tid] + red[3][tid]) / cnt;
    }
    __syncthreads();
    if (tid < NCLS) {
        float s = 0.f;
        #pragma unroll
        for (int c2 = 0; c2 < C2; c2++) s += pooled[c2] * Wc[c2 * NCLS + tid];
        out[g * NCLS + tid] = s + bc[tid];
    }
}

// ---------------- launch: CSR chain || (prepW + gemm1), join before agg1 ----------------
extern "C" void kernel_launch(void* const* d_in, const int* in_sizes, int n_in,
                              void* d_out, int out_size) {
    const float* x     = (const float*)d_in[0];
    const int*   ei    = (const int*)  d_in[1];   // [2, E] row-major
    const int*   batch = (const int*)  d_in[2];
    const float* W1    = (const float*)d_in[3];
    const float* atts1 = (const float*)d_in[4];
    const float* attd1 = (const float*)d_in[5];
    const float* b1    = (const float*)d_in[6];
    const float* W2    = (const float*)d_in[7];
    const float* atts2 = (const float*)d_in[8];
    const float* attd2 = (const float*)d_in[9];
    const float* b2    = (const float*)d_in[10];
    const float* Wc    = (const float*)d_in[11];
    const float* bc    = (const float*)d_in[12];
    float* out = (float*)d_out;

    int gemm_grid = (NN + MB - 1) / MB;   // 1563

    // fresh stream/events per call (never destroyed: kernel_launch runs only a
    // handful of times; destroy-during-capture is illegal). Same work every call.
    cudaStream_t s1;
    cudaEvent_t evF, evJ;
    cudaStreamCreateWithFlags(&s1, cudaStreamNonBlocking);
    cudaEventCreateWithFlags(&evF, cudaEventDisableTiming);
    cudaEventCreateWithFlags(&evJ, cudaEventDisableTiming);

    cudaEventRecord(evF, 0);                   // fork from legacy stream
    cudaStreamWaitEvent(s1, evF, 0);

    // legacy stream: CSR build chain (latency/L2-bound)
    k_hist     <<<(EE / 4 + 255) / 256, 256>>>(ei + EE);
    k_scanA    <<<NCHUNK, 256>>>();
    k_scanC    <<<(NN + 511) / 512, 512>>>();
    k_scatter  <<<(SCAT_E4 + NN + 255) / 256, 256>>>(ei);

    // side stream: weight prep + GEMM1 (tensor-bound), fully independent
    k_prepW    <<<(3072 + 255) / 256, 256, 0, s1>>>(W1, W2);
    k_gemm1    <<<gemm_grid, 256, 0, s1>>>(x, atts1, attd1);

    cudaEventRecord(evJ, s1);                  // join
    cudaStreamWaitEvent(0, evJ, 0);

    k_agg1     <<<(NN * 32 + 255) / 256, 256>>>(b1);
    k_gemm2    <<<gemm_grid, 128>>>(atts2, attd2);
    k_agg2     <<<(NN * 32 + 255) / 256, 256>>>(b2);
    k_poolfinal<<<NGRAPH, 256>>>(batch, Wc, bc, out);
}